// round 1
// baseline (speedup 1.0000x reference)
#include <cuda_runtime.h>
#include <cuda_bf16.h>

// Problem constants (fixed by the dataset):
//   x: [4,4,1024,512] fp32  -> flat [16384, 512]
//   wq/wk/wv/wo: [512,512], biases [512] (zero but applied anyway)
//   reshape to (128, 1024, 64): batch n = contiguous slice at offset n*65536
#define MTOT 16384
#define DIM  512
#define NBATCH 128       // t*b*h
#define SEQ 1024
#define DH 64

// Scratch: q, k, v, attn-out (each 32MB). Device globals = allocation-guard safe.
__device__ __align__(16) float g_buf[4][MTOT * DIM];

// ---------------------------------------------------------------------------
// GEMM: C[M,512] = A[M,512] @ W[512,512] + bias
// Block tile 128x128, K-chunk 16, 256 threads, 8x8 micro-tile.
// SRC/DST < 0 => use external pointer params; otherwise g_buf[SRC]/g_buf[DST].
// ---------------------------------------------------------------------------
template<int SRC, int DST>
__global__ void __launch_bounds__(256, 2) gemm_bias_kernel(
    const float* __restrict__ Aext, const float* __restrict__ W,
    const float* __restrict__ bias, float* __restrict__ Cext)
{
    const float* A = (SRC < 0) ? Aext : g_buf[SRC];
    float*       C = (DST < 0) ? Cext : g_buf[DST];

    __shared__ __align__(16) float As[16][132];   // [k][m], transposed store
    __shared__ __align__(16) float Bs[16][132];   // [k][n]

    const int tid = threadIdx.x;
    const int tx  = tid & 15;          // 0..15 -> 8 cols each
    const int ty  = tid >> 4;          // 0..15 -> 8 rows each
    const int m0  = blockIdx.y * 128;
    const int n0  = blockIdx.x * 128;

    const int arow = tid >> 1;         // 0..127
    const int ak0  = (tid & 1) * 8;    // 0 or 8
    const int brow = tid >> 4;         // 0..15
    const int bcol = (tid & 15) * 8;   // 0..120

    float acc[8][8];
#pragma unroll
    for (int i = 0; i < 8; i++)
#pragma unroll
        for (int j = 0; j < 8; j++) acc[i][j] = 0.f;

    const float* Ap = A + (m0 + arow) * DIM + ak0;
    const float* Wp = W + brow * DIM + n0 + bcol;

    for (int kt = 0; kt < DIM; kt += 16) {
        float4 a0 = *(const float4*)(Ap + kt);
        float4 a1 = *(const float4*)(Ap + kt + 4);
        float4 b0 = *(const float4*)(Wp + kt * DIM);
        float4 b1 = *(const float4*)(Wp + kt * DIM + 4);

        As[ak0 + 0][arow] = a0.x;  As[ak0 + 1][arow] = a0.y;
        As[ak0 + 2][arow] = a0.z;  As[ak0 + 3][arow] = a0.w;
        As[ak0 + 4][arow] = a1.x;  As[ak0 + 5][arow] = a1.y;
        As[ak0 + 6][arow] = a1.z;  As[ak0 + 7][arow] = a1.w;
        *(float4*)&Bs[brow][bcol]     = b0;
        *(float4*)&Bs[brow][bcol + 4] = b1;
        __syncthreads();

#pragma unroll
        for (int k = 0; k < 16; k++) {
            float4 av0 = *(const float4*)&As[k][ty * 8];
            float4 av1 = *(const float4*)&As[k][ty * 8 + 4];
            float4 bv0 = *(const float4*)&Bs[k][tx * 8];
            float4 bv1 = *(const float4*)&Bs[k][tx * 8 + 4];
            float a[8] = {av0.x, av0.y, av0.z, av0.w, av1.x, av1.y, av1.z, av1.w};
            float b[8] = {bv0.x, bv0.y, bv0.z, bv0.w, bv1.x, bv1.y, bv1.z, bv1.w};
#pragma unroll
            for (int i = 0; i < 8; i++)
#pragma unroll
                for (int j = 0; j < 8; j++)
                    acc[i][j] += a[i] * b[j];
        }
        __syncthreads();
    }

    float4 bb0 = *(const float4*)&bias[n0 + tx * 8];
    float4 bb1 = *(const float4*)&bias[n0 + tx * 8 + 4];
#pragma unroll
    for (int i = 0; i < 8; i++) {
        float* crow = C + (m0 + ty * 8 + i) * DIM + n0 + tx * 8;
        float4 o0 = make_float4(acc[i][0] + bb0.x, acc[i][1] + bb0.y,
                                acc[i][2] + bb0.z, acc[i][3] + bb0.w);
        float4 o1 = make_float4(acc[i][4] + bb1.x, acc[i][5] + bb1.y,
                                acc[i][6] + bb1.z, acc[i][7] + bb1.w);
        *(float4*)(crow)     = o0;
        *(float4*)(crow + 4) = o1;
    }
}

// ---------------------------------------------------------------------------
// Flash attention, fp32. One block per (q-tile of 64 rows, batch).
// Bq=64, Bk=32, dh=64, 256 threads as 16x16; S micro-tile 4x2, O micro 4x4.
// Reads g_buf[0..2] (q,k,v), writes g_buf[3].
// ---------------------------------------------------------------------------
__global__ void __launch_bounds__(256) attn_kernel()
{
    __shared__ __align__(16) float Qs[64][68];  // [dh][r]  (transposed)
    __shared__ __align__(16) float Ks[64][34];  // [dh][c]  (transposed)
    __shared__ __align__(16) float Vs[32][68];  // [k][dh]
    __shared__ __align__(16) float Ps[64][34];  // [r][k]

    const int tid = threadIdx.x;
    const int tx  = tid & 15;     // key cols (2 each) / dh cols (4 each)
    const int ty  = tid >> 4;     // q rows (4 each)
    const int n   = blockIdx.y;
    const int qt  = blockIdx.x;

    const float* Qb = g_buf[0] + (size_t)n * (SEQ * DH) + qt * 64 * DH;
    const float* Kb = g_buf[1] + (size_t)n * (SEQ * DH);
    const float* Vb = g_buf[2] + (size_t)n * (SEQ * DH);

    // Load Q tile transposed: 64 rows x 64 dh = 1024 float4 / 256 threads
#pragma unroll
    for (int u = 0; u < 4; u++) {
        int idx = tid + 256 * u;
        int r   = idx >> 4;          // 0..63
        int dq  = (idx & 15) * 4;    // 0..60
        float4 qv = *(const float4*)(Qb + r * DH + dq);
        Qs[dq + 0][r] = qv.x;  Qs[dq + 1][r] = qv.y;
        Qs[dq + 2][r] = qv.z;  Qs[dq + 3][r] = qv.w;
    }

    float m_i[4], l_i[4], o_acc[4][4];
#pragma unroll
    for (int i = 0; i < 4; i++) {
        m_i[i] = -1e30f;
        l_i[i] = 0.f;
#pragma unroll
        for (int j = 0; j < 4; j++) o_acc[i][j] = 0.f;
    }
    const float scale = 0.125f;   // 1/sqrt(64)

    for (int kt = 0; kt < SEQ; kt += 32) {
        __syncthreads();  // guards Ks/Vs overwrite (and Qs stores on iter 0)
#pragma unroll
        for (int u = 0; u < 2; u++) {
            int idx = tid + 256 * u;
            int kr  = idx >> 4;          // 0..31
            int dq  = (idx & 15) * 4;
            float4 kv = *(const float4*)(Kb + (kt + kr) * DH + dq);
            Ks[dq + 0][kr] = kv.x;  Ks[dq + 1][kr] = kv.y;
            Ks[dq + 2][kr] = kv.z;  Ks[dq + 3][kr] = kv.w;
            float4 vv = *(const float4*)(Vb + (kt + kr) * DH + dq);
            *(float4*)&Vs[kr][dq] = vv;
        }
        __syncthreads();

        // S = Q K^T tile: each thread rows ty*4..+3, cols tx*2..+1
        float s[4][2] = {{0.f, 0.f}, {0.f, 0.f}, {0.f, 0.f}, {0.f, 0.f}};
#pragma unroll 16
        for (int kk = 0; kk < 64; kk++) {
            float4 a = *(const float4*)&Qs[kk][ty * 4];
            float2 b = *(const float2*)&Ks[kk][tx * 2];
            s[0][0] += a.x * b.x;  s[0][1] += a.x * b.y;
            s[1][0] += a.y * b.x;  s[1][1] += a.y * b.y;
            s[2][0] += a.z * b.x;  s[2][1] += a.z * b.y;
            s[3][0] += a.w * b.x;  s[3][1] += a.w * b.y;
        }

        // Online softmax (row groups = 16 lanes sharing ty, half-warp shuffles)
#pragma unroll
        for (int i = 0; i < 4; i++) {
            float v0 = s[i][0] * scale, v1 = s[i][1] * scale;
            float mx = fmaxf(v0, v1);
#pragma unroll
            for (int off = 8; off; off >>= 1)
                mx = fmaxf(mx, __shfl_xor_sync(0xffffffffu, mx, off));
            float mn = fmaxf(m_i[i], mx);
            float f  = __expf(m_i[i] - mn);
            float p0 = __expf(v0 - mn);
            float p1 = __expf(v1 - mn);
            float ls = p0 + p1;
#pragma unroll
            for (int off = 8; off; off >>= 1)
                ls += __shfl_xor_sync(0xffffffffu, ls, off);
            l_i[i] = l_i[i] * f + ls;
            m_i[i] = mn;
            o_acc[i][0] *= f;  o_acc[i][1] *= f;
            o_acc[i][2] *= f;  o_acc[i][3] *= f;
            Ps[ty * 4 + i][tx * 2 + 0] = p0;
            Ps[ty * 4 + i][tx * 2 + 1] = p1;
        }
        __syncthreads();

        // O += P V : each thread rows ty*4..+3, dh cols tx*4..+3
#pragma unroll 8
        for (int k = 0; k < 32; k++) {
            float4 vv = *(const float4*)&Vs[k][tx * 4];
            float p0 = Ps[ty * 4 + 0][k];
            float p1 = Ps[ty * 4 + 1][k];
            float p2 = Ps[ty * 4 + 2][k];
            float p3 = Ps[ty * 4 + 3][k];
            o_acc[0][0] += p0 * vv.x;  o_acc[0][1] += p0 * vv.y;
            o_acc[0][2] += p0 * vv.z;  o_acc[0][3] += p0 * vv.w;
            o_acc[1][0] += p1 * vv.x;  o_acc[1][1] += p1 * vv.y;
            o_acc[1][2] += p1 * vv.z;  o_acc[1][3] += p1 * vv.w;
            o_acc[2][0] += p2 * vv.x;  o_acc[2][1] += p2 * vv.y;
            o_acc[2][2] += p2 * vv.z;  o_acc[2][3] += p2 * vv.w;
            o_acc[3][0] += p3 * vv.x;  o_acc[3][1] += p3 * vv.y;
            o_acc[3][2] += p3 * vv.z;  o_acc[3][3] += p3 * vv.w;
        }
    }

    float* Ob = g_buf[3] + (size_t)n * (SEQ * DH) + qt * 64 * DH;
#pragma unroll
    for (int i = 0; i < 4; i++) {
        float inv = 1.0f / l_i[i];
        float4 o = make_float4(o_acc[i][0] * inv, o_acc[i][1] * inv,
                               o_acc[i][2] * inv, o_acc[i][3] * inv);
        *(float4*)&Ob[(ty * 4 + i) * DH + tx * 4] = o;
    }
}

// ---------------------------------------------------------------------------
extern "C" void kernel_launch(void* const* d_in, const int* in_sizes, int n_in,
                              void* d_out, int out_size)
{
    const float* x  = (const float*)d_in[0];
    const float* wq = (const float*)d_in[1];
    const float* bq = (const float*)d_in[2];
    const float* wk = (const float*)d_in[3];
    const float* bk = (const float*)d_in[4];
    const float* wv = (const float*)d_in[5];
    const float* bv = (const float*)d_in[6];
    const float* wo = (const float*)d_in[7];
    const float* bo = (const float*)d_in[8];
    float* out = (float*)d_out;

    dim3 gg(DIM / 128, MTOT / 128);   // (4, 128)

    gemm_bias_kernel<-1, 0><<<gg, 256>>>(x, wq, bq, nullptr);   // q
    gemm_bias_kernel<-1, 1><<<gg, 256>>>(x, wk, bk, nullptr);   // k
    gemm_bias_kernel<-1, 2><<<gg, 256>>>(x, wv, bv, nullptr);   // v
    attn_kernel<<<dim3(SEQ / 64, NBATCH), 256>>>();             // g_buf[3]
    gemm_bias_kernel<3, -1><<<gg, 256>>>(nullptr, wo, bo, out); // output proj
}

// round 3
// speedup vs baseline: 1.3595x; 1.3595x over previous
#include <cuda_runtime.h>
#include <cuda_bf16.h>
#include <cstdint>

#define MTOT 16384
#define DIM  512
#define NBATCH 128
#define SEQ 1024
#define DH 64

// Scratch (device globals = allocation-guard safe)
__device__ __align__(16) float g_buf[4][MTOT * DIM];        // q,k,v,attn-out fp32
__device__ __align__(16) __nv_bfloat16 g_ah[MTOT * DIM];    // A hi split
__device__ __align__(16) __nv_bfloat16 g_al[MTOT * DIM];    // A lo split
__device__ __align__(16) __nv_bfloat16 g_wh[4][DIM * DIM];  // W^T hi (n-major rows, k contiguous)
__device__ __align__(16) __nv_bfloat16 g_wl[4][DIM * DIM];  // W^T lo

// ---------------------------------------------------------------------------
// Helpers: mma.sync bf16 (valid on family-base sm_103 target) + cp.async
// ---------------------------------------------------------------------------
__device__ __forceinline__ uint32_t smem_u32(const void* p) {
    uint32_t a;
    asm("{ .reg .u64 t; cvta.to.shared.u64 t, %1; cvt.u32.u64 %0, t; }" : "=r"(a) : "l"(p));
    return a;
}

#define MMA_BF16(d, a, b0v, b1v)                                               \
    asm volatile("mma.sync.aligned.m16n8k16.row.col.f32.bf16.bf16.f32 "        \
                 "{%0,%1,%2,%3}, {%4,%5,%6,%7}, {%8,%9}, {%0,%1,%2,%3};"       \
                 : "+f"((d)[0]), "+f"((d)[1]), "+f"((d)[2]), "+f"((d)[3])      \
                 : "r"((a)[0]), "r"((a)[1]), "r"((a)[2]), "r"((a)[3]),         \
                   "r"(b0v), "r"(b1v))

__device__ __forceinline__ void cp16(uint32_t dst, const void* src) {
    asm volatile("cp.async.cg.shared.global [%0], [%1], 16;" :: "r"(dst), "l"(src) : "memory");
}
#define CP_COMMIT() asm volatile("cp.async.commit_group;" ::: "memory")
#define CP_WAIT(n)  asm volatile("cp.async.wait_group %0;" :: "n"(n) : "memory")

// ---------------------------------------------------------------------------
// Prep: weight transpose+split, activation split (fp32 -> bf16 hi/lo)
// ---------------------------------------------------------------------------
__global__ void prep_w_kernel(int wsel, const float* __restrict__ W) {
    int idx = blockIdx.x * 256 + threadIdx.x;      // idx = n*512 + k
    int k = idx & (DIM - 1);
    int n = idx >> 9;
    float f = W[k * DIM + n];
    __nv_bfloat16 h = __float2bfloat16(f);
    __nv_bfloat16 l = __float2bfloat16(f - __bfloat162float(h));
    g_wh[wsel][idx] = h;
    g_wl[wsel][idx] = l;
}

template<int SRC>
__global__ void split_kernel(const float* __restrict__ ext) {
    const float* src = (SRC < 0) ? ext : g_buf[SRC];
    int i = blockIdx.x * 256 + threadIdx.x;        // 4 floats per thread
    float4 v = ((const float4*)src)[i];
    float f[4] = {v.x, v.y, v.z, v.w};
    __nv_bfloat16 h[4], l[4];
#pragma unroll
    for (int j = 0; j < 4; j++) {
        h[j] = __float2bfloat16(f[j]);
        l[j] = __float2bfloat16(f[j] - __bfloat162float(h[j]));
    }
    ((__nv_bfloat162*)g_ah)[2 * i]     = __nv_bfloat162(h[0], h[1]);
    ((__nv_bfloat162*)g_ah)[2 * i + 1] = __nv_bfloat162(h[2], h[3]);
    ((__nv_bfloat162*)g_al)[2 * i]     = __nv_bfloat162(l[0], l[1]);
    ((__nv_bfloat162*)g_al)[2 * i + 1] = __nv_bfloat162(l[2], l[3]);
}

// ---------------------------------------------------------------------------
// Tensor-core GEMM via mma.sync: C[16384,512] = A @ W + bias, bf16x3 split.
// CTA tile 128x128, k-chunk 32, double-buffered cp.async staging.
// 8 warps in 4(m) x 2(n); warp tile 32x64; m16n8k16 fragments.
// Smem tiles stored with 40-b16 row stride (conflict-free frag loads).
// ---------------------------------------------------------------------------
#define RS 40                          // row stride in b16 elements (80 bytes)
#define TILE_B (128 * RS * 2)          // 10240 bytes per tile
#define GSM_TOTAL (2 * 4 * TILE_B)     // 81920 bytes dynamic smem

__global__ void __launch_bounds__(256, 2) gemm_mma_kernel(
    int wsel, const float* __restrict__ bias, float* __restrict__ Cext, int dst_sel)
{
    extern __shared__ char smem[];
    const uint32_t sb = smem_u32(smem);
    const int tid  = threadIdx.x;
    const int wid  = tid >> 5;
    const int lane = tid & 31;
    const int g    = lane >> 2;        // 0..7
    const int q    = lane & 3;         // 0..3
    const int wm   = wid >> 1;         // 0..3  -> m offset wm*32
    const int wn   = wid & 1;          // 0..1  -> n offset wn*64
    const int n0   = blockIdx.x * 128;
    const int m0   = blockIdx.y * 128;

    const __nv_bfloat16* __restrict__ Bh = g_wh[wsel];
    const __nv_bfloat16* __restrict__ Bl = g_wl[wsel];
    float* C = (dst_sel < 0) ? Cext : g_buf[dst_sel];

    float acc[2][8][4];
#pragma unroll
    for (int mf = 0; mf < 2; mf++)
#pragma unroll
        for (int nf = 0; nf < 8; nf++)
#pragma unroll
            for (int r = 0; r < 4; r++) acc[mf][nf][r] = 0.f;

    // Stage one k-chunk (A hi/lo + B hi/lo) into buffer `buf` via cp.async.
    auto stage = [&](int buf, int kc) {
        uint32_t base = sb + buf * 4 * TILE_B;
#pragma unroll
        for (int it = 0; it < 2; it++) {
            int gdx = tid + 256 * it;
            int r   = gdx >> 2;
            int qq  = gdx & 3;
            uint32_t doff = (uint32_t)(r * RS * 2 + qq * 16);
            size_t aoff = (size_t)(m0 + r) * DIM + kc + qq * 8;
            size_t boff = (size_t)(n0 + r) * DIM + kc + qq * 8;
            cp16(base + doff,              g_ah + aoff);
            cp16(base + TILE_B + doff,     g_al + aoff);
            cp16(base + 2 * TILE_B + doff, Bh + boff);
            cp16(base + 3 * TILE_B + doff, Bl + boff);
        }
    };

    stage(0, 0);
    CP_COMMIT();

    for (int kt = 0; kt < 16; kt++) {
        if (kt < 15) {
            stage((kt + 1) & 1, (kt + 1) * 32);
            CP_COMMIT();
            CP_WAIT(1);
        } else {
            CP_WAIT(0);
        }
        __syncthreads();

        const char* bufp = smem + (kt & 1) * 4 * TILE_B;
        const __nv_bfloat16* tAh = (const __nv_bfloat16*)(bufp);
        const __nv_bfloat16* tAl = (const __nv_bfloat16*)(bufp + TILE_B);
        const __nv_bfloat16* tBh = (const __nv_bfloat16*)(bufp + 2 * TILE_B);
        const __nv_bfloat16* tBl = (const __nv_bfloat16*)(bufp + 3 * TILE_B);

#pragma unroll
        for (int s = 0; s < 2; s++) {
            const int kb = s * 16;
            uint32_t ah[2][4], al[2][4];
#pragma unroll
            for (int mf = 0; mf < 2; mf++) {
                int r0 = wm * 32 + mf * 16 + g;
                int c0 = kb + 2 * q;
                ah[mf][0] = *(const uint32_t*)(tAh + r0 * RS + c0);
                ah[mf][1] = *(const uint32_t*)(tAh + (r0 + 8) * RS + c0);
                ah[mf][2] = *(const uint32_t*)(tAh + r0 * RS + c0 + 8);
                ah[mf][3] = *(const uint32_t*)(tAh + (r0 + 8) * RS + c0 + 8);
                al[mf][0] = *(const uint32_t*)(tAl + r0 * RS + c0);
                al[mf][1] = *(const uint32_t*)(tAl + (r0 + 8) * RS + c0);
                al[mf][2] = *(const uint32_t*)(tAl + r0 * RS + c0 + 8);
                al[mf][3] = *(const uint32_t*)(tAl + (r0 + 8) * RS + c0 + 8);
            }
#pragma unroll
            for (int nf = 0; nf < 8; nf++) {
                int rb = wn * 64 + nf * 8 + g;
                int cb = kb + 2 * q;
                uint32_t bh0 = *(const uint32_t*)(tBh + rb * RS + cb);
                uint32_t bh1 = *(const uint32_t*)(tBh + rb * RS + cb + 8);
                uint32_t bl0 = *(const uint32_t*)(tBl + rb * RS + cb);
                uint32_t bl1 = *(const uint32_t*)(tBl + rb * RS + cb + 8);
#pragma unroll
                for (int mf = 0; mf < 2; mf++) {
                    MMA_BF16(acc[mf][nf], ah[mf], bh0, bh1);
                    MMA_BF16(acc[mf][nf], ah[mf], bl0, bl1);
                    MMA_BF16(acc[mf][nf], al[mf], bh0, bh1);
                }
            }
        }
        __syncthreads();   // before next stage overwrites this buffer
    }

    // Epilogue: D layout c0,c1 -> (row, 2q..2q+1); c2,c3 -> (row+8, ...)
#pragma unroll
    for (int mf = 0; mf < 2; mf++) {
        int row = m0 + wm * 32 + mf * 16 + g;
#pragma unroll
        for (int nf = 0; nf < 8; nf++) {
            int col = n0 + wn * 64 + nf * 8 + 2 * q;
            float2 bb = *(const float2*)(bias + col);
            float2 o0 = make_float2(acc[mf][nf][0] + bb.x, acc[mf][nf][1] + bb.y);
            float2 o1 = make_float2(acc[mf][nf][2] + bb.x, acc[mf][nf][3] + bb.y);
            *(float2*)(C + (size_t)row * DIM + col)       = o0;
            *(float2*)(C + (size_t)(row + 8) * DIM + col) = o1;
        }
    }
}

// ---------------------------------------------------------------------------
// Flash attention, fp32 SIMT (unchanged; mma.sync port next round)
// ---------------------------------------------------------------------------
__global__ void __launch_bounds__(256) attn_kernel()
{
    __shared__ __align__(16) float Qs[64][68];
    __shared__ __align__(16) float Ks[64][34];
    __shared__ __align__(16) float Vs[32][68];
    __shared__ __align__(16) float Ps[64][34];

    const int tid = threadIdx.x;
    const int tx  = tid & 15;
    const int ty  = tid >> 4;
    const int n   = blockIdx.y;
    const int qt  = blockIdx.x;

    const float* Qb = g_buf[0] + (size_t)n * (SEQ * DH) + qt * 64 * DH;
    const float* Kb = g_buf[1] + (size_t)n * (SEQ * DH);
    const float* Vb = g_buf[2] + (size_t)n * (SEQ * DH);

#pragma unroll
    for (int u = 0; u < 4; u++) {
        int idx = tid + 256 * u;
        int r   = idx >> 4;
        int dq  = (idx & 15) * 4;
        float4 qv = *(const float4*)(Qb + r * DH + dq);
        Qs[dq + 0][r] = qv.x;  Qs[dq + 1][r] = qv.y;
        Qs[dq + 2][r] = qv.z;  Qs[dq + 3][r] = qv.w;
    }

    float m_i[4], l_i[4], o_acc[4][4];
#pragma unroll
    for (int i = 0; i < 4; i++) {
        m_i[i] = -1e30f;
        l_i[i] = 0.f;
#pragma unroll
        for (int j = 0; j < 4; j++) o_acc[i][j] = 0.f;
    }
    const float scale = 0.125f;

    for (int kt = 0; kt < SEQ; kt += 32) {
        __syncthreads();
#pragma unroll
        for (int u = 0; u < 2; u++) {
            int idx = tid + 256 * u;
            int kr  = idx >> 4;
            int dq  = (idx & 15) * 4;
            float4 kv = *(const float4*)(Kb + (kt + kr) * DH + dq);
            Ks[dq + 0][kr] = kv.x;  Ks[dq + 1][kr] = kv.y;
            Ks[dq + 2][kr] = kv.z;  Ks[dq + 3][kr] = kv.w;
            float4 vv = *(const float4*)(Vb + (kt + kr) * DH + dq);
            *(float4*)&Vs[kr][dq] = vv;
        }
        __syncthreads();

        float s[4][2] = {{0.f, 0.f}, {0.f, 0.f}, {0.f, 0.f}, {0.f, 0.f}};
#pragma unroll 16
        for (int kk = 0; kk < 64; kk++) {
            float4 a = *(const float4*)&Qs[kk][ty * 4];
            float2 b = *(const float2*)&Ks[kk][tx * 2];
            s[0][0] += a.x * b.x;  s[0][1] += a.x * b.y;
            s[1][0] += a.y * b.x;  s[1][1] += a.y * b.y;
            s[2][0] += a.z * b.x;  s[2][1] += a.z * b.y;
            s[3][0] += a.w * b.x;  s[3][1] += a.w * b.y;
        }

#pragma unroll
        for (int i = 0; i < 4; i++) {
            float v0 = s[i][0] * scale, v1 = s[i][1] * scale;
            float mx = fmaxf(v0, v1);
#pragma unroll
            for (int off = 8; off; off >>= 1)
                mx = fmaxf(mx, __shfl_xor_sync(0xffffffffu, mx, off));
            float mn = fmaxf(m_i[i], mx);
            float f  = __expf(m_i[i] - mn);
            float p0 = __expf(v0 - mn);
            float p1 = __expf(v1 - mn);
            float ls = p0 + p1;
#pragma unroll
            for (int off = 8; off; off >>= 1)
                ls += __shfl_xor_sync(0xffffffffu, ls, off);
            l_i[i] = l_i[i] * f + ls;
            m_i[i] = mn;
            o_acc[i][0] *= f;  o_acc[i][1] *= f;
            o_acc[i][2] *= f;  o_acc[i][3] *= f;
            Ps[ty * 4 + i][tx * 2 + 0] = p0;
            Ps[ty * 4 + i][tx * 2 + 1] = p1;
        }
        __syncthreads();

#pragma unroll 8
        for (int k = 0; k < 32; k++) {
            float4 vv = *(const float4*)&Vs[k][tx * 4];
            float p0 = Ps[ty * 4 + 0][k];
            float p1 = Ps[ty * 4 + 1][k];
            float p2 = Ps[ty * 4 + 2][k];
            float p3 = Ps[ty * 4 + 3][k];
            o_acc[0][0] += p0 * vv.x;  o_acc[0][1] += p0 * vv.y;
            o_acc[0][2] += p0 * vv.z;  o_acc[0][3] += p0 * vv.w;
            o_acc[1][0] += p1 * vv.x;  o_acc[1][1] += p1 * vv.y;
            o_acc[1][2] += p1 * vv.z;  o_acc[1][3] += p1 * vv.w;
            o_acc[2][0] += p2 * vv.x;  o_acc[2][1] += p2 * vv.y;
            o_acc[2][2] += p2 * vv.z;  o_acc[2][3] += p2 * vv.w;
            o_acc[3][0] += p3 * vv.x;  o_acc[3][1] += p3 * vv.y;
            o_acc[3][2] += p3 * vv.z;  o_acc[3][3] += p3 * vv.w;
        }
    }

    float* Ob = g_buf[3] + (size_t)n * (SEQ * DH) + qt * 64 * DH;
#pragma unroll
    for (int i = 0; i < 4; i++) {
        float inv = 1.0f / l_i[i];
        float4 o = make_float4(o_acc[i][0] * inv, o_acc[i][1] * inv,
                               o_acc[i][2] * inv, o_acc[i][3] * inv);
        *(float4*)&Ob[(ty * 4 + i) * DH + tx * 4] = o;
    }
}

// ---------------------------------------------------------------------------
extern "C" void kernel_launch(void* const* d_in, const int* in_sizes, int n_in,
                              void* d_out, int out_size)
{
    const float* x  = (const float*)d_in[0];
    const float* wq = (const float*)d_in[1];
    const float* bq = (const float*)d_in[2];
    const float* wk = (const float*)d_in[3];
    const float* bk = (const float*)d_in[4];
    const float* wv = (const float*)d_in[5];
    const float* bv = (const float*)d_in[6];
    const float* wo = (const float*)d_in[7];
    const float* bo = (const float*)d_in[8];
    float* out = (float*)d_out;

    static bool attr_set = false;
    if (!attr_set) {
        cudaFuncSetAttribute(gemm_mma_kernel,
                             cudaFuncAttributeMaxDynamicSharedMemorySize, GSM_TOTAL);
        attr_set = true;
    }

    prep_w_kernel<<<1024, 256>>>(0, wq);
    prep_w_kernel<<<1024, 256>>>(1, wk);
    prep_w_kernel<<<1024, 256>>>(2, wv);
    prep_w_kernel<<<1024, 256>>>(3, wo);
    split_kernel<-1><<<8192, 256>>>(x);

    dim3 gg(DIM / 128, MTOT / 128);   // (4, 128)
    gemm_mma_kernel<<<gg, 256, GSM_TOTAL>>>(0, bq, nullptr, 0);   // q
    gemm_mma_kernel<<<gg, 256, GSM_TOTAL>>>(1, bk, nullptr, 1);   // k
    gemm_mma_kernel<<<gg, 256, GSM_TOTAL>>>(2, bv, nullptr, 2);   // v

    attn_kernel<<<dim3(SEQ / 64, NBATCH), 256>>>();               // -> g_buf[3]

    split_kernel<3><<<8192, 256>>>(nullptr);
    gemm_mma_kernel<<<gg, 256, GSM_TOTAL>>>(3, bo, out, -1);      // output proj
}

// round 4
// speedup vs baseline: 2.6511x; 1.9500x over previous
#include <cuda_runtime.h>
#include <cuda_bf16.h>
#include <cstdint>

#define MTOT 16384
#define DIM  512
#define NBATCH 128
#define SEQ 1024
#define DH 64

// Scratch (device globals = allocation-guard safe)
__device__ __align__(16) __nv_bfloat16 g_ah[MTOT * DIM];    // x split hi, later O split hi
__device__ __align__(16) __nv_bfloat16 g_al[MTOT * DIM];    // x split lo, later O split lo
__device__ __align__(16) __nv_bfloat16 g_wh[4][DIM * DIM];  // W^T hi
__device__ __align__(16) __nv_bfloat16 g_wl[4][DIM * DIM];  // W^T lo
__device__ __align__(16) __nv_bfloat16 g_qh[MTOT * DIM], g_ql[MTOT * DIM];
__device__ __align__(16) __nv_bfloat16 g_kh[MTOT * DIM], g_kl[MTOT * DIM];
__device__ __align__(16) __nv_bfloat16 g_vh[MTOT * DIM], g_vl[MTOT * DIM];
__device__ __align__(16) __nv_bfloat16 g_vth[MTOT * DIM], g_vtl[MTOT * DIM]; // V^T [n][dh][seq]

// ---------------------------------------------------------------------------
__device__ __forceinline__ uint32_t smem_u32(const void* p) {
    uint32_t a;
    asm("{ .reg .u64 t; cvta.to.shared.u64 t, %1; cvt.u32.u64 %0, t; }" : "=r"(a) : "l"(p));
    return a;
}

#define MMA_BF16(d, a, b0v, b1v)                                               \
    asm volatile("mma.sync.aligned.m16n8k16.row.col.f32.bf16.bf16.f32 "        \
                 "{%0,%1,%2,%3}, {%4,%5,%6,%7}, {%8,%9}, {%0,%1,%2,%3};"       \
                 : "+f"((d)[0]), "+f"((d)[1]), "+f"((d)[2]), "+f"((d)[3])      \
                 : "r"((a)[0]), "r"((a)[1]), "r"((a)[2]), "r"((a)[3]),         \
                   "r"(b0v), "r"(b1v))

__device__ __forceinline__ void cp16(uint32_t dst, const void* src) {
    asm volatile("cp.async.cg.shared.global [%0], [%1], 16;" :: "r"(dst), "l"(src) : "memory");
}
#define CP_COMMIT() asm volatile("cp.async.commit_group;" ::: "memory")
#define CP_WAIT(n)  asm volatile("cp.async.wait_group %0;" :: "n"(n) : "memory")

__device__ __forceinline__ uint32_t pack_bf16(float a, float b) {
    __nv_bfloat162 t(__float2bfloat16(a), __float2bfloat16(b));
    return *(uint32_t*)&t;
}

// ---------------------------------------------------------------------------
// Prep: weight transpose+split, x split
// ---------------------------------------------------------------------------
__global__ void prep_w_kernel(int wsel, const float* __restrict__ W) {
    int idx = blockIdx.x * 256 + threadIdx.x;      // idx = n*512 + k
    int k = idx & (DIM - 1);
    int n = idx >> 9;
    float f = W[k * DIM + n];
    __nv_bfloat16 h = __float2bfloat16(f);
    __nv_bfloat16 l = __float2bfloat16(f - __bfloat162float(h));
    g_wh[wsel][idx] = h;
    g_wl[wsel][idx] = l;
}

__global__ void split_x_kernel(const float* __restrict__ src) {
    int i = blockIdx.x * 256 + threadIdx.x;        // 4 floats per thread
    float4 v = ((const float4*)src)[i];
    float f[4] = {v.x, v.y, v.z, v.w};
    __nv_bfloat16 h[4], l[4];
#pragma unroll
    for (int j = 0; j < 4; j++) {
        h[j] = __float2bfloat16(f[j]);
        l[j] = __float2bfloat16(f[j] - __bfloat162float(h[j]));
    }
    ((__nv_bfloat162*)g_ah)[2 * i]     = __nv_bfloat162(h[0], h[1]);
    ((__nv_bfloat162*)g_ah)[2 * i + 1] = __nv_bfloat162(h[2], h[3]);
    ((__nv_bfloat162*)g_al)[2 * i]     = __nv_bfloat162(l[0], l[1]);
    ((__nv_bfloat162*)g_al)[2 * i + 1] = __nv_bfloat162(l[2], l[3]);
}

// ---------------------------------------------------------------------------
// V transpose: g_vh/g_vl [n][seq][dh] -> g_vth/g_vtl [n][dh][seq]
// hi+lo packed into one u32 smem tile; pad 65 => conflict-free gather.
// ---------------------------------------------------------------------------
__global__ void __launch_bounds__(256) transpose_v_kernel()
{
    __shared__ uint32_t tile[64][65];
    const int n  = blockIdx.y;
    const int st = blockIdx.x;                    // seq tile of 64
    const int tid = threadIdx.x;
    {
        int s  = tid >> 2;
        int d0 = (tid & 3) * 16;
        const __nv_bfloat16* ph = g_vh + (size_t)n * 65536 + (st * 64 + s) * 64 + d0;
        const __nv_bfloat16* pl = g_vl + (size_t)n * 65536 + (st * 64 + s) * 64 + d0;
        uint4 h0 = *(const uint4*)(ph);
        uint4 h1 = *(const uint4*)(ph + 8);
        uint4 l0 = *(const uint4*)(pl);
        uint4 l1 = *(const uint4*)(pl + 8);
        const uint16_t* hs = (const uint16_t*)&h0;   // h0,h1 contiguous? not guaranteed; handle separately
        const uint16_t* ls = (const uint16_t*)&l0;
#pragma unroll
        for (int j = 0; j < 8; j++)
            tile[s][d0 + j] = (uint32_t)hs[j] | ((uint32_t)ls[j] << 16);
        const uint16_t* hs1 = (const uint16_t*)&h1;
        const uint16_t* ls1 = (const uint16_t*)&l1;
#pragma unroll
        for (int j = 0; j < 8; j++)
            tile[s][d0 + 8 + j] = (uint32_t)hs1[j] | ((uint32_t)ls1[j] << 16);
    }
    __syncthreads();
    {
        int d  = tid >> 2;
        int s0 = (tid & 3) * 16;
        uint16_t hb[16], lb[16];
#pragma unroll
        for (int j = 0; j < 16; j++) {
            uint32_t w = tile[s0 + j][d];
            hb[j] = (uint16_t)(w & 0xFFFF);
            lb[j] = (uint16_t)(w >> 16);
        }
        __nv_bfloat16* oh = g_vth + (size_t)n * 65536 + d * 1024 + st * 64 + s0;
        __nv_bfloat16* ol = g_vtl + (size_t)n * 65536 + d * 1024 + st * 64 + s0;
        *(uint4*)(oh)     = *(uint4*)&hb[0];
        *(uint4*)(oh + 8) = *(uint4*)&hb[8];
        *(uint4*)(ol)     = *(uint4*)&lb[0];
        *(uint4*)(ol + 8) = *(uint4*)&lb[8];
    }
}

// ---------------------------------------------------------------------------
// Tensor-core GEMM: C[16384,512] = A @ W + bias, bf16x3.
// dst_sel: 0/1/2 -> write bf16 hi/lo to q/k/v arrays; <0 -> fp32 to Cext.
// ---------------------------------------------------------------------------
#define RS 40
#define TILE_B (128 * RS * 2)
#define GSM_TOTAL (2 * 4 * TILE_B)     // 81920

__global__ void __launch_bounds__(256, 2) gemm_mma_kernel(
    int wsel, const float* __restrict__ bias, float* __restrict__ Cext, int dst_sel)
{
    extern __shared__ char smem[];
    const uint32_t sb = smem_u32(smem);
    const int tid  = threadIdx.x;
    const int wid  = tid >> 5;
    const int lane = tid & 31;
    const int g    = lane >> 2;
    const int q    = lane & 3;
    const int wm   = wid >> 1;
    const int wn   = wid & 1;
    const int n0   = blockIdx.x * 128;
    const int m0   = blockIdx.y * 128;

    const __nv_bfloat16* __restrict__ Bh = g_wh[wsel];
    const __nv_bfloat16* __restrict__ Bl = g_wl[wsel];

    float acc[2][8][4];
#pragma unroll
    for (int mf = 0; mf < 2; mf++)
#pragma unroll
        for (int nf = 0; nf < 8; nf++)
#pragma unroll
            for (int r = 0; r < 4; r++) acc[mf][nf][r] = 0.f;

    auto stage = [&](int buf, int kc) {
        uint32_t base = sb + buf * 4 * TILE_B;
#pragma unroll
        for (int it = 0; it < 2; it++) {
            int gdx = tid + 256 * it;
            int r   = gdx >> 2;
            int qq  = gdx & 3;
            uint32_t doff = (uint32_t)(r * RS * 2 + qq * 16);
            size_t aoff = (size_t)(m0 + r) * DIM + kc + qq * 8;
            size_t boff = (size_t)(n0 + r) * DIM + kc + qq * 8;
            cp16(base + doff,              g_ah + aoff);
            cp16(base + TILE_B + doff,     g_al + aoff);
            cp16(base + 2 * TILE_B + doff, Bh + boff);
            cp16(base + 3 * TILE_B + doff, Bl + boff);
        }
    };

    stage(0, 0);
    CP_COMMIT();

    for (int kt = 0; kt < 16; kt++) {
        if (kt < 15) {
            stage((kt + 1) & 1, (kt + 1) * 32);
            CP_COMMIT();
            CP_WAIT(1);
        } else {
            CP_WAIT(0);
        }
        __syncthreads();

        const char* bufp = smem + (kt & 1) * 4 * TILE_B;
        const __nv_bfloat16* tAh = (const __nv_bfloat16*)(bufp);
        const __nv_bfloat16* tAl = (const __nv_bfloat16*)(bufp + TILE_B);
        const __nv_bfloat16* tBh = (const __nv_bfloat16*)(bufp + 2 * TILE_B);
        const __nv_bfloat16* tBl = (const __nv_bfloat16*)(bufp + 3 * TILE_B);

#pragma unroll
        for (int s = 0; s < 2; s++) {
            const int kb = s * 16;
            uint32_t ah[2][4], al[2][4];
#pragma unroll
            for (int mf = 0; mf < 2; mf++) {
                int r0 = wm * 32 + mf * 16 + g;
                int c0 = kb + 2 * q;
                ah[mf][0] = *(const uint32_t*)(tAh + r0 * RS + c0);
                ah[mf][1] = *(const uint32_t*)(tAh + (r0 + 8) * RS + c0);
                ah[mf][2] = *(const uint32_t*)(tAh + r0 * RS + c0 + 8);
                ah[mf][3] = *(const uint32_t*)(tAh + (r0 + 8) * RS + c0 + 8);
                al[mf][0] = *(const uint32_t*)(tAl + r0 * RS + c0);
                al[mf][1] = *(const uint32_t*)(tAl + (r0 + 8) * RS + c0);
                al[mf][2] = *(const uint32_t*)(tAl + r0 * RS + c0 + 8);
                al[mf][3] = *(const uint32_t*)(tAl + (r0 + 8) * RS + c0 + 8);
            }
#pragma unroll
            for (int nf = 0; nf < 8; nf++) {
                int rb = wn * 64 + nf * 8 + g;
                int cb = kb + 2 * q;
                uint32_t bh0 = *(const uint32_t*)(tBh + rb * RS + cb);
                uint32_t bh1 = *(const uint32_t*)(tBh + rb * RS + cb + 8);
                uint32_t bl0 = *(const uint32_t*)(tBl + rb * RS + cb);
                uint32_t bl1 = *(const uint32_t*)(tBl + rb * RS + cb + 8);
#pragma unroll
                for (int mf = 0; mf < 2; mf++) {
                    MMA_BF16(acc[mf][nf], ah[mf], bh0, bh1);
                    MMA_BF16(acc[mf][nf], ah[mf], bl0, bl1);
                    MMA_BF16(acc[mf][nf], al[mf], bh0, bh1);
                }
            }
        }
        __syncthreads();
    }

    __nv_bfloat16 *dsth = nullptr, *dstl = nullptr;
    if (dst_sel == 0) { dsth = g_qh; dstl = g_ql; }
    else if (dst_sel == 1) { dsth = g_kh; dstl = g_kl; }
    else if (dst_sel == 2) { dsth = g_vh; dstl = g_vl; }

#pragma unroll
    for (int mf = 0; mf < 2; mf++) {
        int row = m0 + wm * 32 + mf * 16 + g;
#pragma unroll
        for (int nf = 0; nf < 8; nf++) {
            int col = n0 + wn * 64 + nf * 8 + 2 * q;
            float2 bb = *(const float2*)(bias + col);
            float o0 = acc[mf][nf][0] + bb.x, o1 = acc[mf][nf][1] + bb.y;
            float o2 = acc[mf][nf][2] + bb.x, o3 = acc[mf][nf][3] + bb.y;
            if (dst_sel < 0) {
                *(float2*)(Cext + (size_t)row * DIM + col)       = make_float2(o0, o1);
                *(float2*)(Cext + (size_t)(row + 8) * DIM + col) = make_float2(o2, o3);
            } else {
                float h0 = __bfloat162float(__float2bfloat16(o0));
                float h1 = __bfloat162float(__float2bfloat16(o1));
                float h2 = __bfloat162float(__float2bfloat16(o2));
                float h3 = __bfloat162float(__float2bfloat16(o3));
                *(uint32_t*)(dsth + (size_t)row * DIM + col)       = pack_bf16(h0, h1);
                *(uint32_t*)(dsth + (size_t)(row + 8) * DIM + col) = pack_bf16(h2, h3);
                *(uint32_t*)(dstl + (size_t)row * DIM + col)       = pack_bf16(o0 - h0, o1 - h1);
                *(uint32_t*)(dstl + (size_t)(row + 8) * DIM + col) = pack_bf16(o2 - h2, o3 - h3);
            }
        }
    }
}

// ---------------------------------------------------------------------------
// Flash attention via mma.sync, bf16x3 both matmuls.
// CTA: 128 q-rows x batch; 8 warps, warp = 16 rows x full 64-key tile.
// Q frags in registers (loop-invariant). P reused from S frags (no smem).
// K/Vt staged double-buffered via cp.async, row stride 72 b16.
// ---------------------------------------------------------------------------
#define AKS 72
#define ATILE (64 * AKS * 2)              // 9216 B per array
#define ASTG  (4 * ATILE)                 // 36864 per stage
#define ASM_TOTAL (2 * ASTG)              // 73728

__global__ void __launch_bounds__(256) attn_mma_kernel()
{
    extern __shared__ char smem[];
    const uint32_t sb = smem_u32(smem);
    const int tid  = threadIdx.x;
    const int wid  = tid >> 5;
    const int lane = tid & 31;
    const int g    = lane >> 2;
    const int q    = lane & 3;
    const int n    = blockIdx.y;
    const int qt   = blockIdx.x;

    const size_t nb = (size_t)n * 65536;
    const __nv_bfloat16* qhp = g_qh + nb + (qt * 128) * 64;
    const __nv_bfloat16* qlp = g_ql + nb + (qt * 128) * 64;

    // Q fragments (loop-invariant): rows wid*16+g, +8; cols ks*16+2q (+8)
    uint32_t qah[4][4], qal[4][4];
    const int r0 = wid * 16 + g, r1 = r0 + 8;
#pragma unroll
    for (int ks = 0; ks < 4; ks++) {
        int c = ks * 16 + 2 * q;
        qah[ks][0] = *(const uint32_t*)(qhp + r0 * 64 + c);
        qah[ks][1] = *(const uint32_t*)(qhp + r1 * 64 + c);
        qah[ks][2] = *(const uint32_t*)(qhp + r0 * 64 + c + 8);
        qah[ks][3] = *(const uint32_t*)(qhp + r1 * 64 + c + 8);
        qal[ks][0] = *(const uint32_t*)(qlp + r0 * 64 + c);
        qal[ks][1] = *(const uint32_t*)(qlp + r1 * 64 + c);
        qal[ks][2] = *(const uint32_t*)(qlp + r0 * 64 + c + 8);
        qal[ks][3] = *(const uint32_t*)(qlp + r1 * 64 + c + 8);
    }

    float oacc[8][4];
#pragma unroll
    for (int i = 0; i < 8; i++)
#pragma unroll
        for (int j = 0; j < 4; j++) oacc[i][j] = 0.f;
    float m0 = -1e30f, m1 = -1e30f, l0 = 0.f, l1 = 0.f;

    // stage arrays: 0=Kh 1=Kl 2=Vth 3=Vtl
    auto stage = [&](int buf, int kt) {
        uint32_t base = sb + buf * ASTG;
#pragma unroll
        for (int it = 0; it < 2; it++) {
            int gdx = tid + 256 * it;
            int r  = gdx >> 3;           // 0..63
            int qq = gdx & 7;            // 0..7
            uint32_t doff = (uint32_t)(r * (AKS * 2) + qq * 16);
            size_t koff = nb + (size_t)(kt * 64 + r) * 64 + qq * 8;
            size_t voff = nb + (size_t)r * 1024 + kt * 64 + qq * 8;
            cp16(base + doff,             g_kh + koff);
            cp16(base + ATILE + doff,     g_kl + koff);
            cp16(base + 2 * ATILE + doff, g_vth + voff);
            cp16(base + 3 * ATILE + doff, g_vtl + voff);
        }
    };

    stage(0, 0);
    CP_COMMIT();

    const float scale = 0.125f;
    for (int kt = 0; kt < 16; kt++) {
        if (kt < 15) {
            stage((kt + 1) & 1, kt + 1);
            CP_COMMIT();
            CP_WAIT(1);
        } else {
            CP_WAIT(0);
        }
        __syncthreads();

        const char* bufp = smem + (kt & 1) * ASTG;
        const __nv_bfloat16* tKh = (const __nv_bfloat16*)(bufp);
        const __nv_bfloat16* tKl = (const __nv_bfloat16*)(bufp + ATILE);
        const __nv_bfloat16* tVh = (const __nv_bfloat16*)(bufp + 2 * ATILE);
        const __nv_bfloat16* tVl = (const __nv_bfloat16*)(bufp + 3 * ATILE);

        // S = Q K^T (bf16x3)
        float s[8][4];
#pragma unroll
        for (int nf = 0; nf < 8; nf++)
#pragma unroll
            for (int j = 0; j < 4; j++) s[nf][j] = 0.f;

#pragma unroll
        for (int ks = 0; ks < 4; ks++) {
#pragma unroll
            for (int nf = 0; nf < 8; nf++) {
                int rb = nf * 8 + g;
                int cb = ks * 16 + 2 * q;
                uint32_t bh0 = *(const uint32_t*)(tKh + rb * AKS + cb);
                uint32_t bh1 = *(const uint32_t*)(tKh + rb * AKS + cb + 8);
                uint32_t bl0 = *(const uint32_t*)(tKl + rb * AKS + cb);
                uint32_t bl1 = *(const uint32_t*)(tKl + rb * AKS + cb + 8);
                MMA_BF16(s[nf], qah[ks], bh0, bh1);
                MMA_BF16(s[nf], qah[ks], bl0, bl1);
                MMA_BF16(s[nf], qal[ks], bh0, bh1);
            }
        }

        // Online softmax. Rows: r0 owns c0,c1 ; r1 owns c2,c3.
        float mn0 = m0, mn1 = m1;
#pragma unroll
        for (int nf = 0; nf < 8; nf++) {
#pragma unroll
            for (int j = 0; j < 4; j++) s[nf][j] *= scale;
            mn0 = fmaxf(mn0, fmaxf(s[nf][0], s[nf][1]));
            mn1 = fmaxf(mn1, fmaxf(s[nf][2], s[nf][3]));
        }
#pragma unroll
        for (int off = 1; off <= 2; off <<= 1) {
            mn0 = fmaxf(mn0, __shfl_xor_sync(0xffffffffu, mn0, off));
            mn1 = fmaxf(mn1, __shfl_xor_sync(0xffffffffu, mn1, off));
        }
        float f0 = __expf(m0 - mn0), f1 = __expf(m1 - mn1);
        m0 = mn0;  m1 = mn1;

        uint32_t ph[8], ph2[8], pl[8], pl2[8];
        float ls0 = 0.f, ls1 = 0.f;
#pragma unroll
        for (int nf = 0; nf < 8; nf++) {
            float p0 = __expf(s[nf][0] - m0);
            float p1 = __expf(s[nf][1] - m0);
            float p2 = __expf(s[nf][2] - m1);
            float p3 = __expf(s[nf][3] - m1);
            ls0 += p0 + p1;  ls1 += p2 + p3;
            float h0 = __bfloat162float(__float2bfloat16(p0));
            float h1 = __bfloat162float(__float2bfloat16(p1));
            float h2 = __bfloat162float(__float2bfloat16(p2));
            float h3 = __bfloat162float(__float2bfloat16(p3));
            ph[nf]  = pack_bf16(h0, h1);
            ph2[nf] = pack_bf16(h2, h3);
            pl[nf]  = pack_bf16(p0 - h0, p1 - h1);
            pl2[nf] = pack_bf16(p2 - h2, p3 - h3);
        }
#pragma unroll
        for (int off = 1; off <= 2; off <<= 1) {
            ls0 += __shfl_xor_sync(0xffffffffu, ls0, off);
            ls1 += __shfl_xor_sync(0xffffffffu, ls1, off);
        }
        l0 = l0 * f0 + ls0;
        l1 = l1 * f1 + ls1;
#pragma unroll
        for (int dhf = 0; dhf < 8; dhf++) {
            oacc[dhf][0] *= f0;  oacc[dhf][1] *= f0;
            oacc[dhf][2] *= f1;  oacc[dhf][3] *= f1;
        }

        // O += P V (bf16x3): A-frags come straight from P registers
#pragma unroll
        for (int ks = 0; ks < 4; ks++) {
            uint32_t a_h[4] = {ph[2 * ks], ph2[2 * ks], ph[2 * ks + 1], ph2[2 * ks + 1]};
            uint32_t a_l[4] = {pl[2 * ks], pl2[2 * ks], pl[2 * ks + 1], pl2[2 * ks + 1]};
#pragma unroll
            for (int dhf = 0; dhf < 8; dhf++) {
                int rb = dhf * 8 + g;
                int cb = ks * 16 + 2 * q;
                uint32_t bh0 = *(const uint32_t*)(tVh + rb * AKS + cb);
                uint32_t bh1 = *(const uint32_t*)(tVh + rb * AKS + cb + 8);
                uint32_t bl0 = *(const uint32_t*)(tVl + rb * AKS + cb);
                uint32_t bl1 = *(const uint32_t*)(tVl + rb * AKS + cb + 8);
                MMA_BF16(oacc[dhf], a_h, bh0, bh1);
                MMA_BF16(oacc[dhf], a_h, bl0, bl1);
                MMA_BF16(oacc[dhf], a_l, bh0, bh1);
            }
        }
        __syncthreads();
    }

    // Epilogue: O/l, split to bf16 hi/lo into g_ah/g_al for the final GEMM.
    float inv0 = 1.0f / l0, inv1 = 1.0f / l1;
    const size_t ob0 = nb + (size_t)(qt * 128 + r0) * 64;
    const size_t ob1 = nb + (size_t)(qt * 128 + r1) * 64;
#pragma unroll
    for (int dhf = 0; dhf < 8; dhf++) {
        int col = dhf * 8 + 2 * q;
        float o0 = oacc[dhf][0] * inv0, o1 = oacc[dhf][1] * inv0;
        float o2 = oacc[dhf][2] * inv1, o3 = oacc[dhf][3] * inv1;
        float h0 = __bfloat162float(__float2bfloat16(o0));
        float h1 = __bfloat162float(__float2bfloat16(o1));
        float h2 = __bfloat162float(__float2bfloat16(o2));
        float h3 = __bfloat162float(__float2bfloat16(o3));
        *(uint32_t*)(g_ah + ob0 + col) = pack_bf16(h0, h1);
        *(uint32_t*)(g_ah + ob1 + col) = pack_bf16(h2, h3);
        *(uint32_t*)(g_al + ob0 + col) = pack_bf16(o0 - h0, o1 - h1);
        *(uint32_t*)(g_al + ob1 + col) = pack_bf16(o2 - h2, o3 - h3);
    }
}

// ---------------------------------------------------------------------------
extern "C" void kernel_launch(void* const* d_in, const int* in_sizes, int n_in,
                              void* d_out, int out_size)
{
    const float* x  = (const float*)d_in[0];
    const float* wq = (const float*)d_in[1];
    const float* bq = (const float*)d_in[2];
    const float* wk = (const float*)d_in[3];
    const float* bk = (const float*)d_in[4];
    const float* wv = (const float*)d_in[5];
    const float* bv = (const float*)d_in[6];
    const float* wo = (const float*)d_in[7];
    const float* bo = (const float*)d_in[8];
    float* out = (float*)d_out;

    static bool attr_set = false;
    if (!attr_set) {
        cudaFuncSetAttribute(gemm_mma_kernel,
                             cudaFuncAttributeMaxDynamicSharedMemorySize, GSM_TOTAL);
        cudaFuncSetAttribute(attn_mma_kernel,
                             cudaFuncAttributeMaxDynamicSharedMemorySize, ASM_TOTAL);
        attr_set = true;
    }

    prep_w_kernel<<<1024, 256>>>(0, wq);
    prep_w_kernel<<<1024, 256>>>(1, wk);
    prep_w_kernel<<<1024, 256>>>(2, wv);
    prep_w_kernel<<<1024, 256>>>(3, wo);
    split_x_kernel<<<8192, 256>>>(x);

    dim3 gg(DIM / 128, MTOT / 128);   // (4, 128)
    gemm_mma_kernel<<<gg, 256, GSM_TOTAL>>>(0, bq, nullptr, 0);   // q -> bf16 hi/lo
    gemm_mma_kernel<<<gg, 256, GSM_TOTAL>>>(1, bk, nullptr, 1);   // k
    gemm_mma_kernel<<<gg, 256, GSM_TOTAL>>>(2, bv, nullptr, 2);   // v

    transpose_v_kernel<<<dim3(16, NBATCH), 256>>>();              // Vt hi/lo

    attn_mma_kernel<<<dim3(8, NBATCH), 256, ASM_TOTAL>>>();       // O -> g_ah/g_al

    gemm_mma_kernel<<<gg, 256, GSM_TOTAL>>>(3, bo, out, -1);      // output proj
}

// round 8
// speedup vs baseline: 2.8012x; 1.0566x over previous
#include <cuda_runtime.h>
#include <cuda_bf16.h>
#include <cstdint>

#define MTOT 16384
#define DIM  512
#define NBATCH 128
#define SEQ 1024
#define DH 64

// Scratch (device globals = allocation-guard safe)
__device__ __align__(16) __nv_bfloat16 g_ah[MTOT * DIM];    // x split hi, later O split hi
__device__ __align__(16) __nv_bfloat16 g_al[MTOT * DIM];    // x split lo, later O split lo
__device__ __align__(16) __nv_bfloat16 g_wh[4][DIM * DIM];  // W^T hi
__device__ __align__(16) __nv_bfloat16 g_wl[4][DIM * DIM];  // W^T lo
__device__ __align__(16) __nv_bfloat16 g_qh[MTOT * DIM], g_ql[MTOT * DIM];
__device__ __align__(16) __nv_bfloat16 g_kh[MTOT * DIM], g_kl[MTOT * DIM];
__device__ __align__(16) __nv_bfloat16 g_vh[MTOT * DIM], g_vl[MTOT * DIM];
__device__ __align__(16) __nv_bfloat16 g_vth[MTOT * DIM], g_vtl[MTOT * DIM]; // V^T [n][dh][seq]

// ---------------------------------------------------------------------------
__device__ __forceinline__ uint32_t smem_u32(const void* p) {
    uint32_t a;
    asm("{ .reg .u64 t; cvta.to.shared.u64 t, %1; cvt.u32.u64 %0, t; }" : "=r"(a) : "l"(p));
    return a;
}

#define MMA_BF16(d, a, b0v, b1v)                                               \
    asm volatile("mma.sync.aligned.m16n8k16.row.col.f32.bf16.bf16.f32 "        \
                 "{%0,%1,%2,%3}, {%4,%5,%6,%7}, {%8,%9}, {%0,%1,%2,%3};"       \
                 : "+f"((d)[0]), "+f"((d)[1]), "+f"((d)[2]), "+f"((d)[3])      \
                 : "r"((a)[0]), "r"((a)[1]), "r"((a)[2]), "r"((a)[3]),         \
                   "r"(b0v), "r"(b1v))

__device__ __forceinline__ void cp16(uint32_t dst, const void* src) {
    asm volatile("cp.async.cg.shared.global [%0], [%1], 16;" :: "r"(dst), "l"(src) : "memory");
}
#define CP_COMMIT() asm volatile("cp.async.commit_group;" ::: "memory")
#define CP_WAIT(n)  asm volatile("cp.async.wait_group %0;" :: "n"(n) : "memory")

__device__ __forceinline__ uint32_t pack_bf16(float a, float b) {
    __nv_bfloat162 t(__float2bfloat16(a), __float2bfloat16(b));
    return *(uint32_t*)&t;
}

// ---------------------------------------------------------------------------
// Prep: all 4 weight transposes+splits in one launch (blockIdx.y = wsel)
// ---------------------------------------------------------------------------
__global__ void prep_w_kernel(const float* __restrict__ w0, const float* __restrict__ w1,
                              const float* __restrict__ w2, const float* __restrict__ w3) {
    const int wsel = blockIdx.y;
    const float* W = (wsel == 0) ? w0 : (wsel == 1) ? w1 : (wsel == 2) ? w2 : w3;
    int idx = blockIdx.x * 256 + threadIdx.x;      // idx = n*512 + k
    int k = idx & (DIM - 1);
    int n = idx >> 9;
    float f = W[k * DIM + n];
    __nv_bfloat16 h = __float2bfloat16(f);
    __nv_bfloat16 l = __float2bfloat16(f - __bfloat162float(h));
    g_wh[wsel][idx] = h;
    g_wl[wsel][idx] = l;
}

__global__ void split_x_kernel(const float* __restrict__ src) {
    int i = blockIdx.x * 256 + threadIdx.x;        // 4 floats per thread
    float4 v = ((const float4*)src)[i];
    float f[4] = {v.x, v.y, v.z, v.w};
    __nv_bfloat16 h[4], l[4];
#pragma unroll
    for (int j = 0; j < 4; j++) {
        h[j] = __float2bfloat16(f[j]);
        l[j] = __float2bfloat16(f[j] - __bfloat162float(h[j]));
    }
    ((__nv_bfloat162*)g_ah)[2 * i]     = __nv_bfloat162(h[0], h[1]);
    ((__nv_bfloat162*)g_ah)[2 * i + 1] = __nv_bfloat162(h[2], h[3]);
    ((__nv_bfloat162*)g_al)[2 * i]     = __nv_bfloat162(l[0], l[1]);
    ((__nv_bfloat162*)g_al)[2 * i + 1] = __nv_bfloat162(l[2], l[3]);
}

// ---------------------------------------------------------------------------
// V transpose (known-good round-4 version):
// g_vh/g_vl [n][seq][dh] (== flat GEMM layout) -> g_vth/g_vtl [n][dh][seq]
// ---------------------------------------------------------------------------
__global__ void __launch_bounds__(256) transpose_v_kernel()
{
    __shared__ uint32_t tile[64][65];
    const int n  = blockIdx.y;
    const int st = blockIdx.x;                    // seq tile of 64
    const int tid = threadIdx.x;
    {
        int s  = tid >> 2;
        int d0 = (tid & 3) * 16;
        const __nv_bfloat16* ph = g_vh + (size_t)n * 65536 + (st * 64 + s) * 64 + d0;
        const __nv_bfloat16* pl = g_vl + (size_t)n * 65536 + (st * 64 + s) * 64 + d0;
        uint4 h0 = *(const uint4*)(ph);
        uint4 h1 = *(const uint4*)(ph + 8);
        uint4 l0 = *(const uint4*)(pl);
        uint4 l1 = *(const uint4*)(pl + 8);
        const uint16_t* hs = (const uint16_t*)&h0;
        const uint16_t* ls = (const uint16_t*)&l0;
#pragma unroll
        for (int j = 0; j < 8; j++)
            tile[s][d0 + j] = (uint32_t)hs[j] | ((uint32_t)ls[j] << 16);
        const uint16_t* hs1 = (const uint16_t*)&h1;
        const uint16_t* ls1 = (const uint16_t*)&l1;
#pragma unroll
        for (int j = 0; j < 8; j++)
            tile[s][d0 + 8 + j] = (uint32_t)hs1[j] | ((uint32_t)ls1[j] << 16);
    }
    __syncthreads();
    {
        int d  = tid >> 2;
        int s0 = (tid & 3) * 16;
        uint16_t hb[16], lb[16];
#pragma unroll
        for (int j = 0; j < 16; j++) {
            uint32_t w = tile[s0 + j][d];
            hb[j] = (uint16_t)(w & 0xFFFF);
            lb[j] = (uint16_t)(w >> 16);
        }
        __nv_bfloat16* oh = g_vth + (size_t)n * 65536 + d * 1024 + st * 64 + s0;
        __nv_bfloat16* ol = g_vtl + (size_t)n * 65536 + d * 1024 + st * 64 + s0;
        *(uint4*)(oh)     = *(uint4*)&hb[0];
        *(uint4*)(oh + 8) = *(uint4*)&hb[8];
        *(uint4*)(ol)     = *(uint4*)&lb[0];
        *(uint4*)(ol + 8) = *(uint4*)&lb[8];
    }
}

// ---------------------------------------------------------------------------
// Tensor-core GEMM: C[16384,512] = A @ W + bias, bf16x3.
// Fused Q/K/V: blockIdx.z = dst_sel (0=q,1=k,2=v). dst_override<0: wsel=3, fp32 out.
// ---------------------------------------------------------------------------
#define RS 40
#define TILE_B (128 * RS * 2)
#define GSM_TOTAL (2 * 4 * TILE_B)     // 81920

__global__ void __launch_bounds__(256, 2) gemm_mma_kernel(
    const float* __restrict__ bq, const float* __restrict__ bk,
    const float* __restrict__ bv, float* __restrict__ Cext, int dst_override)
{
    extern __shared__ char smem[];
    const uint32_t sb = smem_u32(smem);
    const int tid  = threadIdx.x;
    const int wid  = tid >> 5;
    const int lane = tid & 31;
    const int g    = lane >> 2;
    const int q    = lane & 3;
    const int wm   = wid >> 1;
    const int wn   = wid & 1;
    const int n0   = blockIdx.x * 128;
    const int m0   = blockIdx.y * 128;

    const int dst_sel = (dst_override < 0) ? -1 : (int)blockIdx.z;
    const int wsel    = (dst_override < 0) ? 3 : (int)blockIdx.z;
    const float* bias = (dst_override < 0) ? bq
                        : (dst_sel == 0) ? bq : (dst_sel == 1) ? bk : bv;

    const __nv_bfloat16* __restrict__ Bh = g_wh[wsel];
    const __nv_bfloat16* __restrict__ Bl = g_wl[wsel];

    float acc[2][8][4];
#pragma unroll
    for (int mf = 0; mf < 2; mf++)
#pragma unroll
        for (int nf = 0; nf < 8; nf++)
#pragma unroll
            for (int r = 0; r < 4; r++) acc[mf][nf][r] = 0.f;

    auto stage = [&](int buf, int kc) {
        uint32_t base = sb + buf * 4 * TILE_B;
#pragma unroll
        for (int it = 0; it < 2; it++) {
            int gdx = tid + 256 * it;
            int r   = gdx >> 2;
            int qq  = gdx & 3;
            uint32_t doff = (uint32_t)(r * RS * 2 + qq * 16);
            size_t aoff = (size_t)(m0 + r) * DIM + kc + qq * 8;
            size_t boff = (size_t)(n0 + r) * DIM + kc + qq * 8;
            cp16(base + doff,              g_ah + aoff);
            cp16(base + TILE_B + doff,     g_al + aoff);
            cp16(base + 2 * TILE_B + doff, Bh + boff);
            cp16(base + 3 * TILE_B + doff, Bl + boff);
        }
    };

    stage(0, 0);
    CP_COMMIT();

    for (int kt = 0; kt < 16; kt++) {
        if (kt < 15) {
            stage((kt + 1) & 1, (kt + 1) * 32);
            CP_COMMIT();
            CP_WAIT(1);
        } else {
            CP_WAIT(0);
        }
        __syncthreads();

        const char* bufp = smem + (kt & 1) * 4 * TILE_B;
        const __nv_bfloat16* tAh = (const __nv_bfloat16*)(bufp);
        const __nv_bfloat16* tAl = (const __nv_bfloat16*)(bufp + TILE_B);
        const __nv_bfloat16* tBh = (const __nv_bfloat16*)(bufp + 2 * TILE_B);
        const __nv_bfloat16* tBl = (const __nv_bfloat16*)(bufp + 3 * TILE_B);

#pragma unroll
        for (int s = 0; s < 2; s++) {
            const int kb = s * 16;
            uint32_t ah[2][4], al[2][4];
#pragma unroll
            for (int mf = 0; mf < 2; mf++) {
                int r0 = wm * 32 + mf * 16 + g;
                int c0 = kb + 2 * q;
                ah[mf][0] = *(const uint32_t*)(tAh + r0 * RS + c0);
                ah[mf][1] = *(const uint32_t*)(tAh + (r0 + 8) * RS + c0);
                ah[mf][2] = *(const uint32_t*)(tAh + r0 * RS + c0 + 8);
                ah[mf][3] = *(const uint32_t*)(tAh + (r0 + 8) * RS + c0 + 8);
                al[mf][0] = *(const uint32_t*)(tAl + r0 * RS + c0);
                al[mf][1] = *(const uint32_t*)(tAl + (r0 + 8) * RS + c0);
                al[mf][2] = *(const uint32_t*)(tAl + r0 * RS + c0 + 8);
                al[mf][3] = *(const uint32_t*)(tAl + (r0 + 8) * RS + c0 + 8);
            }
#pragma unroll
            for (int nf = 0; nf < 8; nf++) {
                int rb = wn * 64 + nf * 8 + g;
                int cb = kb + 2 * q;
                uint32_t bh0 = *(const uint32_t*)(tBh + rb * RS + cb);
                uint32_t bh1 = *(const uint32_t*)(tBh + rb * RS + cb + 8);
                uint32_t bl0 = *(const uint32_t*)(tBl + rb * RS + cb);
                uint32_t bl1 = *(const uint32_t*)(tBl + rb * RS + cb + 8);
#pragma unroll
                for (int mf = 0; mf < 2; mf++) {
                    MMA_BF16(acc[mf][nf], ah[mf], bh0, bh1);
                    MMA_BF16(acc[mf][nf], ah[mf], bl0, bl1);
                    MMA_BF16(acc[mf][nf], al[mf], bh0, bh1);
                }
            }
        }
        __syncthreads();
    }

    __nv_bfloat16 *dsth = nullptr, *dstl = nullptr;
    if (dst_sel == 0) { dsth = g_qh; dstl = g_ql; }
    else if (dst_sel == 1) { dsth = g_kh; dstl = g_kl; }
    else if (dst_sel == 2) { dsth = g_vh; dstl = g_vl; }

#pragma unroll
    for (int mf = 0; mf < 2; mf++) {
        int row = m0 + wm * 32 + mf * 16 + g;
#pragma unroll
        for (int nf = 0; nf < 8; nf++) {
            int col = n0 + wn * 64 + nf * 8 + 2 * q;
            float2 bb = *(const float2*)(bias + col);
            float o0 = acc[mf][nf][0] + bb.x, o1 = acc[mf][nf][1] + bb.y;
            float o2 = acc[mf][nf][2] + bb.x, o3 = acc[mf][nf][3] + bb.y;
            if (dst_sel < 0) {
                *(float2*)(Cext + (size_t)row * DIM + col)       = make_float2(o0, o1);
                *(float2*)(Cext + (size_t)(row + 8) * DIM + col) = make_float2(o2, o3);
            } else {
                float h0 = __bfloat162float(__float2bfloat16(o0));
                float h1 = __bfloat162float(__float2bfloat16(o1));
                float h2 = __bfloat162float(__float2bfloat16(o2));
                float h3 = __bfloat162float(__float2bfloat16(o3));
                *(uint32_t*)(dsth + (size_t)row * DIM + col)       = pack_bf16(h0, h1);
                *(uint32_t*)(dsth + (size_t)(row + 8) * DIM + col) = pack_bf16(h2, h3);
                *(uint32_t*)(dstl + (size_t)row * DIM + col)       = pack_bf16(o0 - h0, o1 - h1);
                *(uint32_t*)(dstl + (size_t)(row + 8) * DIM + col) = pack_bf16(o2 - h2, o3 - h3);
            }
        }
    }
}

// ---------------------------------------------------------------------------
// Flash attention via mma.sync, bf16x3 on BOTH matmuls (full Pl*Vh term —
// dropping it measured rel_err 1.7e-3, over the gate).
// ---------------------------------------------------------------------------
#define AKS 72
#define ATILE (64 * AKS * 2)              // 9216 B per array
#define ASTG  (4 * ATILE)                 // 36864 per stage
#define ASM_TOTAL (2 * ASTG)              // 73728

__global__ void __launch_bounds__(256) attn_mma_kernel()
{
    extern __shared__ char smem[];
    const uint32_t sb = smem_u32(smem);
    const int tid  = threadIdx.x;
    const int wid  = tid >> 5;
    const int lane = tid & 31;
    const int g    = lane >> 2;
    const int q    = lane & 3;
    const int n    = blockIdx.y;
    const int qt   = blockIdx.x;

    const size_t nb = (size_t)n * 65536;
    const __nv_bfloat16* qhp = g_qh + nb + (qt * 128) * 64;
    const __nv_bfloat16* qlp = g_ql + nb + (qt * 128) * 64;

    uint32_t qah[4][4], qal[4][4];
    const int r0 = wid * 16 + g, r1 = r0 + 8;
#pragma unroll
    for (int ks = 0; ks < 4; ks++) {
        int c = ks * 16 + 2 * q;
        qah[ks][0] = *(const uint32_t*)(qhp + r0 * 64 + c);
        qah[ks][1] = *(const uint32_t*)(qhp + r1 * 64 + c);
        qah[ks][2] = *(const uint32_t*)(qhp + r0 * 64 + c + 8);
        qah[ks][3] = *(const uint32_t*)(qhp + r1 * 64 + c + 8);
        qal[ks][0] = *(const uint32_t*)(qlp + r0 * 64 + c);
        qal[ks][1] = *(const uint32_t*)(qlp + r1 * 64 + c);
        qal[ks][2] = *(const uint32_t*)(qlp + r0 * 64 + c + 8);
        qal[ks][3] = *(const uint32_t*)(qlp + r1 * 64 + c + 8);
    }

    float oacc[8][4];
#pragma unroll
    for (int i = 0; i < 8; i++)
#pragma unroll
        for (int j = 0; j < 4; j++) oacc[i][j] = 0.f;
    float m0 = -1e30f, m1 = -1e30f, l0 = 0.f, l1 = 0.f;

    auto stage = [&](int buf, int kt) {
        uint32_t base = sb + buf * ASTG;
#pragma unroll
        for (int it = 0; it < 2; it++) {
            int gdx = tid + 256 * it;
            int r  = gdx >> 3;
            int qq = gdx & 7;
            uint32_t doff = (uint32_t)(r * (AKS * 2) + qq * 16);
            size_t koff = nb + (size_t)(kt * 64 + r) * 64 + qq * 8;
            size_t voff = nb + (size_t)r * 1024 + kt * 64 + qq * 8;
            cp16(base + doff,             g_kh + koff);
            cp16(base + ATILE + doff,     g_kl + koff);
            cp16(base + 2 * ATILE + doff, g_vth + voff);
            cp16(base + 3 * ATILE + doff, g_vtl + voff);
        }
    };

    stage(0, 0);
    CP_COMMIT();

    const float scale = 0.125f;
    for (int kt = 0; kt < 16; kt++) {
        if (kt < 15) {
            stage((kt + 1) & 1, kt + 1);
            CP_COMMIT();
            CP_WAIT(1);
        } else {
            CP_WAIT(0);
        }
        __syncthreads();

        const char* bufp = smem + (kt & 1) * ASTG;
        const __nv_bfloat16* tKh = (const __nv_bfloat16*)(bufp);
        const __nv_bfloat16* tKl = (const __nv_bfloat16*)(bufp + ATILE);
        const __nv_bfloat16* tVh = (const __nv_bfloat16*)(bufp + 2 * ATILE);
        const __nv_bfloat16* tVl = (const __nv_bfloat16*)(bufp + 3 * ATILE);

        float s[8][4];
#pragma unroll
        for (int nf = 0; nf < 8; nf++)
#pragma unroll
            for (int j = 0; j < 4; j++) s[nf][j] = 0.f;

#pragma unroll
        for (int ks = 0; ks < 4; ks++) {
#pragma unroll
            for (int nf = 0; nf < 8; nf++) {
                int rb = nf * 8 + g;
                int cb = ks * 16 + 2 * q;
                uint32_t bh0 = *(const uint32_t*)(tKh + rb * AKS + cb);
                uint32_t bh1 = *(const uint32_t*)(tKh + rb * AKS + cb + 8);
                uint32_t bl0 = *(const uint32_t*)(tKl + rb * AKS + cb);
                uint32_t bl1 = *(const uint32_t*)(tKl + rb * AKS + cb + 8);
                MMA_BF16(s[nf], qah[ks], bh0, bh1);
                MMA_BF16(s[nf], qah[ks], bl0, bl1);
                MMA_BF16(s[nf], qal[ks], bh0, bh1);
            }
        }

        float mn0 = m0, mn1 = m1;
#pragma unroll
        for (int nf = 0; nf < 8; nf++) {
#pragma unroll
            for (int j = 0; j < 4; j++) s[nf][j] *= scale;
            mn0 = fmaxf(mn0, fmaxf(s[nf][0], s[nf][1]));
            mn1 = fmaxf(mn1, fmaxf(s[nf][2], s[nf][3]));
        }
#pragma unroll
        for (int off = 1; off <= 2; off <<= 1) {
            mn0 = fmaxf(mn0, __shfl_xor_sync(0xffffffffu, mn0, off));
            mn1 = fmaxf(mn1, __shfl_xor_sync(0xffffffffu, mn1, off));
        }
        float f0 = __expf(m0 - mn0), f1 = __expf(m1 - mn1);
        m0 = mn0;  m1 = mn1;

        uint32_t ph[8], ph2[8], pl[8], pl2[8];
        float ls0 = 0.f, ls1 = 0.f;
#pragma unroll
        for (int nf = 0; nf < 8; nf++) {
            float p0 = __expf(s[nf][0] - m0);
            float p1 = __expf(s[nf][1] - m0);
            float p2 = __expf(s[nf][2] - m1);
            float p3 = __expf(s[nf][3] - m1);
            ls0 += p0 + p1;  ls1 += p2 + p3;
            float h0 = __bfloat162float(__float2bfloat16(p0));
            float h1 = __bfloat162float(__float2bfloat16(p1));
            float h2 = __bfloat162float(__float2bfloat16(p2));
            float h3 = __bfloat162float(__float2bfloat16(p3));
            ph[nf]  = pack_bf16(h0, h1);
            ph2[nf] = pack_bf16(h2, h3);
            pl[nf]  = pack_bf16(p0 - h0, p1 - h1);
            pl2[nf] = pack_bf16(p2 - h2, p3 - h3);
        }
#pragma unroll
        for (int off = 1; off <= 2; off <<= 1) {
            ls0 += __shfl_xor_sync(0xffffffffu, ls0, off);
            ls1 += __shfl_xor_sync(0xffffffffu, ls1, off);
        }
        l0 = l0 * f0 + ls0;
        l1 = l1 * f1 + ls1;
#pragma unroll
        for (int dhf = 0; dhf < 8; dhf++) {
            oacc[dhf][0] *= f0;  oacc[dhf][1] *= f0;
            oacc[dhf][2] *= f1;  oacc[dhf][3] *= f1;
        }

        // O += P V, bf16x3: Ph*Vh + Ph*Vl + Pl*Vh
#pragma unroll
        for (int ks = 0; ks < 4; ks++) {
            uint32_t a_h[4] = {ph[2 * ks], ph2[2 * ks], ph[2 * ks + 1], ph2[2 * ks + 1]};
            uint32_t a_l[4] = {pl[2 * ks], pl2[2 * ks], pl[2 * ks + 1], pl2[2 * ks + 1]};
#pragma unroll
            for (int dhf = 0; dhf < 8; dhf++) {
                int rb = dhf * 8 + g;
                int cb = ks * 16 + 2 * q;
                uint32_t bh0 = *(const uint32_t*)(tVh + rb * AKS + cb);
                uint32_t bh1 = *(const uint32_t*)(tVh + rb * AKS + cb + 8);
                uint32_t bl0 = *(const uint32_t*)(tVl + rb * AKS + cb);
                uint32_t bl1 = *(const uint32_t*)(tVl + rb * AKS + cb + 8);
                MMA_BF16(oacc[dhf], a_h, bh0, bh1);
                MMA_BF16(oacc[dhf], a_h, bl0, bl1);
                MMA_BF16(oacc[dhf], a_l, bh0, bh1);
            }
        }
        __syncthreads();
    }

    float inv0 = 1.0f / l0, inv1 = 1.0f / l1;
    const size_t ob0 = nb + (size_t)(qt * 128 + r0) * 64;
    const size_t ob1 = nb + (size_t)(qt * 128 + r1) * 64;
#pragma unroll
    for (int dhf = 0; dhf < 8; dhf++) {
        int col = dhf * 8 + 2 * q;
        float o0 = oacc[dhf][0] * inv0, o1 = oacc[dhf][1] * inv0;
        float o2 = oacc[dhf][2] * inv1, o3 = oacc[dhf][3] * inv1;
        float h0 = __bfloat162float(__float2bfloat16(o0));
        float h1 = __bfloat162float(__float2bfloat16(o1));
        float h2 = __bfloat162float(__float2bfloat16(o2));
        float h3 = __bfloat162float(__float2bfloat16(o3));
        *(uint32_t*)(g_ah + ob0 + col) = pack_bf16(h0, h1);
        *(uint32_t*)(g_ah + ob1 + col) = pack_bf16(h2, h3);
        *(uint32_t*)(g_al + ob0 + col) = pack_bf16(o0 - h0, o1 - h1);
        *(uint32_t*)(g_al + ob1 + col) = pack_bf16(o2 - h2, o3 - h3);
    }
}

// ---------------------------------------------------------------------------
extern "C" void kernel_launch(void* const* d_in, const int* in_sizes, int n_in,
                              void* d_out, int out_size)
{
    const float* x  = (const float*)d_in[0];
    const float* wq = (const float*)d_in[1];
    const float* bq = (const float*)d_in[2];
    const float* wk = (const float*)d_in[3];
    const float* bk = (const float*)d_in[4];
    const float* wv = (const float*)d_in[5];
    const float* bv = (const float*)d_in[6];
    const float* wo = (const float*)d_in[7];
    const float* bo = (const float*)d_in[8];
    float* out = (float*)d_out;

    static bool attr_set = false;
    if (!attr_set) {
        cudaFuncSetAttribute(gemm_mma_kernel,
                             cudaFuncAttributeMaxDynamicSharedMemorySize, GSM_TOTAL);
        cudaFuncSetAttribute(attn_mma_kernel,
                             cudaFuncAttributeMaxDynamicSharedMemorySize, ASM_TOTAL);
        attr_set = true;
    }

    prep_w_kernel<<<dim3(1024, 4), 256>>>(wq, wk, wv, wo);
    split_x_kernel<<<8192, 256>>>(x);

    // Fused Q/K/V projections: blockIdx.z selects weight + destination
    gemm_mma_kernel<<<dim3(4, 128, 3), 256, GSM_TOTAL>>>(bq, bk, bv, nullptr, 0);

    transpose_v_kernel<<<dim3(16, NBATCH), 256>>>();              // Vt hi/lo

    attn_mma_kernel<<<dim3(8, NBATCH), 256, ASM_TOTAL>>>();       // O -> g_ah/g_al

    // Output projection (wsel=3, fp32 out)
    gemm_mma_kernel<<<dim3(4, 128, 1), 256, GSM_TOTAL>>>(bo, nullptr, nullptr, out, -1);
}

// round 9
// speedup vs baseline: 3.1076x; 1.1094x over previous
#include <cuda_runtime.h>
#include <cuda_bf16.h>
#include <cstdint>

#define MTOT 16384
#define DIM  512
#define NBATCH 128
#define SEQ 1024
#define DH 64

// Scratch (device globals = allocation-guard safe)
__device__ __align__(16) __nv_bfloat16 g_ah[MTOT * DIM];    // x split hi, later O split hi
__device__ __align__(16) __nv_bfloat16 g_al[MTOT * DIM];    // x split lo, later O split lo
__device__ __align__(16) __nv_bfloat16 g_wh[4][DIM * DIM];  // W^T hi
__device__ __align__(16) __nv_bfloat16 g_wl[4][DIM * DIM];  // W^T lo
__device__ __align__(16) __nv_bfloat16 g_qh[MTOT * DIM], g_ql[MTOT * DIM];
__device__ __align__(16) __nv_bfloat16 g_kh[MTOT * DIM], g_kl[MTOT * DIM];
__device__ __align__(16) __nv_bfloat16 g_vh[MTOT * DIM], g_vl[MTOT * DIM];
__device__ __align__(16) __nv_bfloat16 g_vth[MTOT * DIM], g_vtl[MTOT * DIM]; // V^T [n][dh][seq]

// ---------------------------------------------------------------------------
__device__ __forceinline__ uint32_t smem_u32(const void* p) {
    uint32_t a;
    asm("{ .reg .u64 t; cvta.to.shared.u64 t, %1; cvt.u32.u64 %0, t; }" : "=r"(a) : "l"(p));
    return a;
}

#define MMA_BF16(d, a, b0v, b1v)                                               \
    asm volatile("mma.sync.aligned.m16n8k16.row.col.f32.bf16.bf16.f32 "        \
                 "{%0,%1,%2,%3}, {%4,%5,%6,%7}, {%8,%9}, {%0,%1,%2,%3};"       \
                 : "+f"((d)[0]), "+f"((d)[1]), "+f"((d)[2]), "+f"((d)[3])      \
                 : "r"((a)[0]), "r"((a)[1]), "r"((a)[2]), "r"((a)[3]),         \
                   "r"(b0v), "r"(b1v))

// ldmatrix x4: lanes 0-7 supply rows of matrix0, 8-15 m1, 16-23 m2, 24-31 m3.
#define LDSM_X4(r0, r1, r2, r3, addr)                                          \
    asm volatile("ldmatrix.sync.aligned.m8n8.x4.shared.b16 {%0,%1,%2,%3}, [%4];" \
                 : "=r"(r0), "=r"(r1), "=r"(r2), "=r"(r3) : "r"(addr))

__device__ __forceinline__ void cp16(uint32_t dst, const void* src) {
    asm volatile("cp.async.cg.shared.global [%0], [%1], 16;" :: "r"(dst), "l"(src) : "memory");
}
#define CP_COMMIT() asm volatile("cp.async.commit_group;" ::: "memory")
#define CP_WAIT(n)  asm volatile("cp.async.wait_group %0;" :: "n"(n) : "memory")

__device__ __forceinline__ uint32_t pack_bf16(float a, float b) {
    __nv_bfloat162 t(__float2bfloat16(a), __float2bfloat16(b));
    return *(uint32_t*)&t;
}

// ---------------------------------------------------------------------------
// Prep: all 4 weight transposes+splits in one launch. wq gets softmax scale
// 0.125 folded in (S = (0.125 q) k^T arrives pre-scaled).
// ---------------------------------------------------------------------------
__global__ void prep_w_kernel(const float* __restrict__ w0, const float* __restrict__ w1,
                              const float* __restrict__ w2, const float* __restrict__ w3) {
    const int wsel = blockIdx.y;
    const float* W = (wsel == 0) ? w0 : (wsel == 1) ? w1 : (wsel == 2) ? w2 : w3;
    int idx = blockIdx.x * 256 + threadIdx.x;      // idx = n*512 + k
    int k = idx & (DIM - 1);
    int n = idx >> 9;
    float f = W[k * DIM + n];
    if (wsel == 0) f *= 0.125f;
    __nv_bfloat16 h = __float2bfloat16(f);
    __nv_bfloat16 l = __float2bfloat16(f - __bfloat162float(h));
    g_wh[wsel][idx] = h;
    g_wl[wsel][idx] = l;
}

__global__ void split_x_kernel(const float* __restrict__ src) {
    int i = blockIdx.x * 256 + threadIdx.x;        // 4 floats per thread
    float4 v = ((const float4*)src)[i];
    float f[4] = {v.x, v.y, v.z, v.w};
    __nv_bfloat16 h[4], l[4];
#pragma unroll
    for (int j = 0; j < 4; j++) {
        h[j] = __float2bfloat16(f[j]);
        l[j] = __float2bfloat16(f[j] - __bfloat162float(h[j]));
    }
    ((__nv_bfloat162*)g_ah)[2 * i]     = __nv_bfloat162(h[0], h[1]);
    ((__nv_bfloat162*)g_ah)[2 * i + 1] = __nv_bfloat162(h[2], h[3]);
    ((__nv_bfloat162*)g_al)[2 * i]     = __nv_bfloat162(l[0], l[1]);
    ((__nv_bfloat162*)g_al)[2 * i + 1] = __nv_bfloat162(l[2], l[3]);
}

// ---------------------------------------------------------------------------
// V transpose: g_vh/g_vl [n][seq][dh] -> g_vth/g_vtl [n][dh][seq]
// ---------------------------------------------------------------------------
__global__ void __launch_bounds__(256) transpose_v_kernel()
{
    __shared__ uint32_t tile[64][65];
    const int n  = blockIdx.y;
    const int st = blockIdx.x;
    const int tid = threadIdx.x;
    {
        int s  = tid >> 2;
        int d0 = (tid & 3) * 16;
        const __nv_bfloat16* ph = g_vh + (size_t)n * 65536 + (st * 64 + s) * 64 + d0;
        const __nv_bfloat16* pl = g_vl + (size_t)n * 65536 + (st * 64 + s) * 64 + d0;
        uint4 h0 = *(const uint4*)(ph);
        uint4 h1 = *(const uint4*)(ph + 8);
        uint4 l0 = *(const uint4*)(pl);
        uint4 l1 = *(const uint4*)(pl + 8);
        const uint16_t* hs = (const uint16_t*)&h0;
        const uint16_t* ls = (const uint16_t*)&l0;
#pragma unroll
        for (int j = 0; j < 8; j++)
            tile[s][d0 + j] = (uint32_t)hs[j] | ((uint32_t)ls[j] << 16);
        const uint16_t* hs1 = (const uint16_t*)&h1;
        const uint16_t* ls1 = (const uint16_t*)&l1;
#pragma unroll
        for (int j = 0; j < 8; j++)
            tile[s][d0 + 8 + j] = (uint32_t)hs1[j] | ((uint32_t)ls1[j] << 16);
    }
    __syncthreads();
    {
        int d  = tid >> 2;
        int s0 = (tid & 3) * 16;
        uint16_t hb[16], lb[16];
#pragma unroll
        for (int j = 0; j < 16; j++) {
            uint32_t w = tile[s0 + j][d];
            hb[j] = (uint16_t)(w & 0xFFFF);
            lb[j] = (uint16_t)(w >> 16);
        }
        __nv_bfloat16* oh = g_vth + (size_t)n * 65536 + d * 1024 + st * 64 + s0;
        __nv_bfloat16* ol = g_vtl + (size_t)n * 65536 + d * 1024 + st * 64 + s0;
        *(uint4*)(oh)     = *(uint4*)&hb[0];
        *(uint4*)(oh + 8) = *(uint4*)&hb[8];
        *(uint4*)(ol)     = *(uint4*)&lb[0];
        *(uint4*)(ol + 8) = *(uint4*)&lb[8];
    }
}

// ---------------------------------------------------------------------------
// Tensor-core GEMM, bf16x3, ldmatrix fragment loads.
// ---------------------------------------------------------------------------
#define RS 40
#define TILE_B (128 * RS * 2)
#define GSM_TOTAL (2 * 4 * TILE_B)     // 81920

__global__ void __launch_bounds__(256, 2) gemm_mma_kernel(
    const float* __restrict__ bq, const float* __restrict__ bk,
    const float* __restrict__ bv, float* __restrict__ Cext, int dst_override)
{
    extern __shared__ char smem[];
    const uint32_t sb = smem_u32(smem);
    const int tid  = threadIdx.x;
    const int wid  = tid >> 5;
    const int lane = tid & 31;
    const int g    = lane >> 2;
    const int q    = lane & 3;
    const int lj   = lane >> 3;        // ldmatrix matrix index
    const int li   = lane & 7;         // ldmatrix row-within-matrix
    const int wm   = wid >> 1;
    const int wn   = wid & 1;
    const int n0   = blockIdx.x * 128;
    const int m0   = blockIdx.y * 128;

    const int dst_sel = (dst_override < 0) ? -1 : (int)blockIdx.z;
    const int wsel    = (dst_override < 0) ? 3 : (int)blockIdx.z;
    const float* bias = (dst_override < 0) ? bq
                        : (dst_sel == 0) ? bq : (dst_sel == 1) ? bk : bv;
    const float bscale = (dst_sel == 0) ? 0.125f : 1.0f;   // fold softmax scale

    const __nv_bfloat16* __restrict__ Bh = g_wh[wsel];
    const __nv_bfloat16* __restrict__ Bl = g_wl[wsel];

    float acc[2][8][4];
#pragma unroll
    for (int mf = 0; mf < 2; mf++)
#pragma unroll
        for (int nf = 0; nf < 8; nf++)
#pragma unroll
            for (int r = 0; r < 4; r++) acc[mf][nf][r] = 0.f;

    auto stage = [&](int buf, int kc) {
        uint32_t base = sb + buf * 4 * TILE_B;
#pragma unroll
        for (int it = 0; it < 2; it++) {
            int gdx = tid + 256 * it;
            int r   = gdx >> 2;
            int qq  = gdx & 3;
            uint32_t doff = (uint32_t)(r * RS * 2 + qq * 16);
            size_t aoff = (size_t)(m0 + r) * DIM + kc + qq * 8;
            size_t boff = (size_t)(n0 + r) * DIM + kc + qq * 8;
            cp16(base + doff,              g_ah + aoff);
            cp16(base + TILE_B + doff,     g_al + aoff);
            cp16(base + 2 * TILE_B + doff, Bh + boff);
            cp16(base + 3 * TILE_B + doff, Bl + boff);
        }
    };

    stage(0, 0);
    CP_COMMIT();

    // Per-lane ldmatrix address components (element offsets; *2 for bytes)
    // A-frag (m16k16): matrix j -> row +((j&1)<<3), kcol +((j>>1)<<3)
    const int a_row_lane = ((lj & 1) << 3) + li;
    const int a_col_lane = (lj >> 1) << 3;
    // B-frag pair (two n8k16): matrix j -> row +((j>>1)<<3), kcol +((j&1)<<3)
    const int b_row_lane = ((lj >> 1) << 3) + li;
    const int b_col_lane = (lj & 1) << 3;

    for (int kt = 0; kt < 16; kt++) {
        if (kt < 15) {
            stage((kt + 1) & 1, (kt + 1) * 32);
            CP_COMMIT();
            CP_WAIT(1);
        } else {
            CP_WAIT(0);
        }
        __syncthreads();

        const uint32_t base = sb + (kt & 1) * 4 * TILE_B;
        const uint32_t bAh = base, bAl = base + TILE_B;
        const uint32_t bBh = base + 2 * TILE_B, bBl = base + 3 * TILE_B;

#pragma unroll
        for (int s = 0; s < 2; s++) {
            const int kb = s * 16;
            uint32_t ah[2][4], al[2][4];
#pragma unroll
            for (int mf = 0; mf < 2; mf++) {
                uint32_t ro = (uint32_t)((wm * 32 + mf * 16 + a_row_lane) * RS
                                         + kb + a_col_lane) * 2;
                LDSM_X4(ah[mf][0], ah[mf][1], ah[mf][2], ah[mf][3], bAh + ro);
                LDSM_X4(al[mf][0], al[mf][1], al[mf][2], al[mf][3], bAl + ro);
            }
#pragma unroll
            for (int nfp = 0; nfp < 4; nfp++) {
                uint32_t ro = (uint32_t)((wn * 64 + nfp * 16 + b_row_lane) * RS
                                         + kb + b_col_lane) * 2;
                uint32_t h0, h1, h2, h3, l0, l1, l2, l3;
                LDSM_X4(h0, h1, h2, h3, bBh + ro);
                LDSM_X4(l0, l1, l2, l3, bBl + ro);
#pragma unroll
                for (int mf = 0; mf < 2; mf++) {
                    MMA_BF16(acc[mf][2 * nfp],     ah[mf], h0, h1);
                    MMA_BF16(acc[mf][2 * nfp],     ah[mf], l0, l1);
                    MMA_BF16(acc[mf][2 * nfp],     al[mf], h0, h1);
                    MMA_BF16(acc[mf][2 * nfp + 1], ah[mf], h2, h3);
                    MMA_BF16(acc[mf][2 * nfp + 1], ah[mf], l2, l3);
                    MMA_BF16(acc[mf][2 * nfp + 1], al[mf], h2, h3);
                }
            }
        }
        __syncthreads();
    }

    __nv_bfloat16 *dsth = nullptr, *dstl = nullptr;
    if (dst_sel == 0) { dsth = g_qh; dstl = g_ql; }
    else if (dst_sel == 1) { dsth = g_kh; dstl = g_kl; }
    else if (dst_sel == 2) { dsth = g_vh; dstl = g_vl; }

#pragma unroll
    for (int mf = 0; mf < 2; mf++) {
        int row = m0 + wm * 32 + mf * 16 + g;
#pragma unroll
        for (int nf = 0; nf < 8; nf++) {
            int col = n0 + wn * 64 + nf * 8 + 2 * q;
            float2 bb = *(const float2*)(bias + col);
            bb.x *= bscale;  bb.y *= bscale;
            float o0 = acc[mf][nf][0] + bb.x, o1 = acc[mf][nf][1] + bb.y;
            float o2 = acc[mf][nf][2] + bb.x, o3 = acc[mf][nf][3] + bb.y;
            if (dst_sel < 0) {
                *(float2*)(Cext + (size_t)row * DIM + col)       = make_float2(o0, o1);
                *(float2*)(Cext + (size_t)(row + 8) * DIM + col) = make_float2(o2, o3);
            } else {
                float h0 = __bfloat162float(__float2bfloat16(o0));
                float h1 = __bfloat162float(__float2bfloat16(o1));
                float h2 = __bfloat162float(__float2bfloat16(o2));
                float h3 = __bfloat162float(__float2bfloat16(o3));
                *(uint32_t*)(dsth + (size_t)row * DIM + col)       = pack_bf16(h0, h1);
                *(uint32_t*)(dsth + (size_t)(row + 8) * DIM + col) = pack_bf16(h2, h3);
                *(uint32_t*)(dstl + (size_t)row * DIM + col)       = pack_bf16(o0 - h0, o1 - h1);
                *(uint32_t*)(dstl + (size_t)(row + 8) * DIM + col) = pack_bf16(o2 - h2, o3 - h3);
            }
        }
    }
}

// ---------------------------------------------------------------------------
// Flash attention via mma.sync, bf16x3 both matmuls, ldmatrix frag loads.
// Scale pre-folded into Q. 2 CTAs/SM target.
// ---------------------------------------------------------------------------
#define AKS 72
#define ATILE (64 * AKS * 2)              // 9216 B per array
#define ASTG  (4 * ATILE)                 // 36864 per stage
#define ASM_TOTAL (2 * ASTG)              // 73728

__global__ void __launch_bounds__(256, 2) attn_mma_kernel()
{
    extern __shared__ char smem[];
    const uint32_t sb = smem_u32(smem);
    const int tid  = threadIdx.x;
    const int wid  = tid >> 5;
    const int lane = tid & 31;
    const int g    = lane >> 2;
    const int q    = lane & 3;
    const int lj   = lane >> 3;
    const int li   = lane & 7;
    const int n    = blockIdx.y;
    const int qt   = blockIdx.x;

    const size_t nb = (size_t)n * 65536;
    const __nv_bfloat16* qhp = g_qh + nb + (qt * 128) * 64;
    const __nv_bfloat16* qlp = g_ql + nb + (qt * 128) * 64;

    uint32_t qah[4][4], qal[4][4];
    const int r0 = wid * 16 + g, r1 = r0 + 8;
#pragma unroll
    for (int ks = 0; ks < 4; ks++) {
        int c = ks * 16 + 2 * q;
        qah[ks][0] = *(const uint32_t*)(qhp + r0 * 64 + c);
        qah[ks][1] = *(const uint32_t*)(qhp + r1 * 64 + c);
        qah[ks][2] = *(const uint32_t*)(qhp + r0 * 64 + c + 8);
        qah[ks][3] = *(const uint32_t*)(qhp + r1 * 64 + c + 8);
        qal[ks][0] = *(const uint32_t*)(qlp + r0 * 64 + c);
        qal[ks][1] = *(const uint32_t*)(qlp + r1 * 64 + c);
        qal[ks][2] = *(const uint32_t*)(qlp + r0 * 64 + c + 8);
        qal[ks][3] = *(const uint32_t*)(qlp + r1 * 64 + c + 8);
    }

    float oacc[8][4];
#pragma unroll
    for (int i = 0; i < 8; i++)
#pragma unroll
        for (int j = 0; j < 4; j++) oacc[i][j] = 0.f;
    float m0 = -1e30f, m1 = -1e30f, l0 = 0.f, l1 = 0.f;

    auto stage = [&](int buf, int kt) {
        uint32_t base = sb + buf * ASTG;
#pragma unroll
        for (int it = 0; it < 2; it++) {
            int gdx = tid + 256 * it;
            int r  = gdx >> 3;
            int qq = gdx & 7;
            uint32_t doff = (uint32_t)(r * (AKS * 2) + qq * 16);
            size_t koff = nb + (size_t)(kt * 64 + r) * 64 + qq * 8;
            size_t voff = nb + (size_t)r * 1024 + kt * 64 + qq * 8;
            cp16(base + doff,             g_kh + koff);
            cp16(base + ATILE + doff,     g_kl + koff);
            cp16(base + 2 * ATILE + doff, g_vth + voff);
            cp16(base + 3 * ATILE + doff, g_vtl + voff);
        }
    };

    stage(0, 0);
    CP_COMMIT();

    const int b_row_lane = ((lj >> 1) << 3) + li;
    const int b_col_lane = (lj & 1) << 3;

    for (int kt = 0; kt < 16; kt++) {
        if (kt < 15) {
            stage((kt + 1) & 1, kt + 1);
            CP_COMMIT();
            CP_WAIT(1);
        } else {
            CP_WAIT(0);
        }
        __syncthreads();

        const uint32_t base = sb + (kt & 1) * ASTG;
        const uint32_t bKh = base, bKl = base + ATILE;
        const uint32_t bVh = base + 2 * ATILE, bVl = base + 3 * ATILE;

        // S = Q K^T (bf16x3), pre-scaled
        float s[8][4];
#pragma unroll
        for (int nf = 0; nf < 8; nf++)
#pragma unroll
            for (int j = 0; j < 4; j++) s[nf][j] = 0.f;

#pragma unroll
        for (int ks = 0; ks < 4; ks++) {
#pragma unroll
            for (int nfp = 0; nfp < 4; nfp++) {
                uint32_t ro = (uint32_t)((nfp * 16 + b_row_lane) * AKS
                                         + ks * 16 + b_col_lane) * 2;
                uint32_t h0, h1, h2, h3, l0r, l1r, l2r, l3r;
                LDSM_X4(h0, h1, h2, h3, bKh + ro);
                LDSM_X4(l0r, l1r, l2r, l3r, bKl + ro);
                MMA_BF16(s[2 * nfp],     qah[ks], h0, h1);
                MMA_BF16(s[2 * nfp],     qah[ks], l0r, l1r);
                MMA_BF16(s[2 * nfp],     qal[ks], h0, h1);
                MMA_BF16(s[2 * nfp + 1], qah[ks], h2, h3);
                MMA_BF16(s[2 * nfp + 1], qah[ks], l2r, l3r);
                MMA_BF16(s[2 * nfp + 1], qal[ks], h2, h3);
            }
        }

        float mn0 = m0, mn1 = m1;
#pragma unroll
        for (int nf = 0; nf < 8; nf++) {
            mn0 = fmaxf(mn0, fmaxf(s[nf][0], s[nf][1]));
            mn1 = fmaxf(mn1, fmaxf(s[nf][2], s[nf][3]));
        }
#pragma unroll
        for (int off = 1; off <= 2; off <<= 1) {
            mn0 = fmaxf(mn0, __shfl_xor_sync(0xffffffffu, mn0, off));
            mn1 = fmaxf(mn1, __shfl_xor_sync(0xffffffffu, mn1, off));
        }
        float f0 = __expf(m0 - mn0), f1 = __expf(m1 - mn1);
        m0 = mn0;  m1 = mn1;

        uint32_t ph[8], ph2[8], pl[8], pl2[8];
        float ls0 = 0.f, ls1 = 0.f;
#pragma unroll
        for (int nf = 0; nf < 8; nf++) {
            float p0 = __expf(s[nf][0] - m0);
            float p1 = __expf(s[nf][1] - m0);
            float p2 = __expf(s[nf][2] - m1);
            float p3 = __expf(s[nf][3] - m1);
            ls0 += p0 + p1;  ls1 += p2 + p3;
            float h0 = __bfloat162float(__float2bfloat16(p0));
            float h1 = __bfloat162float(__float2bfloat16(p1));
            float h2 = __bfloat162float(__float2bfloat16(p2));
            float h3 = __bfloat162float(__float2bfloat16(p3));
            ph[nf]  = pack_bf16(h0, h1);
            ph2[nf] = pack_bf16(h2, h3);
            pl[nf]  = pack_bf16(p0 - h0, p1 - h1);
            pl2[nf] = pack_bf16(p2 - h2, p3 - h3);
        }
#pragma unroll
        for (int off = 1; off <= 2; off <<= 1) {
            ls0 += __shfl_xor_sync(0xffffffffu, ls0, off);
            ls1 += __shfl_xor_sync(0xffffffffu, ls1, off);
        }
        l0 = l0 * f0 + ls0;
        l1 = l1 * f1 + ls1;
#pragma unroll
        for (int dhf = 0; dhf < 8; dhf++) {
            oacc[dhf][0] *= f0;  oacc[dhf][1] *= f0;
            oacc[dhf][2] *= f1;  oacc[dhf][3] *= f1;
        }

        // O += P V, bf16x3: Ph*Vh + Ph*Vl + Pl*Vh
#pragma unroll
        for (int ks = 0; ks < 4; ks++) {
            uint32_t a_h[4] = {ph[2 * ks], ph2[2 * ks], ph[2 * ks + 1], ph2[2 * ks + 1]};
            uint32_t a_l[4] = {pl[2 * ks], pl2[2 * ks], pl[2 * ks + 1], pl2[2 * ks + 1]};
#pragma unroll
            for (int dhp = 0; dhp < 4; dhp++) {
                uint32_t ro = (uint32_t)((dhp * 16 + b_row_lane) * AKS
                                         + ks * 16 + b_col_lane) * 2;
                uint32_t h0, h1, h2, h3, l0r, l1r, l2r, l3r;
                LDSM_X4(h0, h1, h2, h3, bVh + ro);
                LDSM_X4(l0r, l1r, l2r, l3r, bVl + ro);
                MMA_BF16(oacc[2 * dhp],     a_h, h0, h1);
                MMA_BF16(oacc[2 * dhp],     a_h, l0r, l1r);
                MMA_BF16(oacc[2 * dhp],     a_l, h0, h1);
                MMA_BF16(oacc[2 * dhp + 1], a_h, h2, h3);
                MMA_BF16(oacc[2 * dhp + 1], a_h, l2r, l3r);
                MMA_BF16(oacc[2 * dhp + 1], a_l, h2, h3);
            }
        }
        __syncthreads();
    }

    float inv0 = 1.0f / l0, inv1 = 1.0f / l1;
    const size_t ob0 = nb + (size_t)(qt * 128 + r0) * 64;
    const size_t ob1 = nb + (size_t)(qt * 128 + r1) * 64;
#pragma unroll
    for (int dhf = 0; dhf < 8; dhf++) {
        int col = dhf * 8 + 2 * q;
        float o0 = oacc[dhf][0] * inv0, o1 = oacc[dhf][1] * inv0;
        float o2 = oacc[dhf][2] * inv1, o3 = oacc[dhf][3] * inv1;
        float h0 = __bfloat162float(__float2bfloat16(o0));
        float h1 = __bfloat162float(__float2bfloat16(o1));
        float h2 = __bfloat162float(__float2bfloat16(o2));
        float h3 = __bfloat162float(__float2bfloat16(o3));
        *(uint32_t*)(g_ah + ob0 + col) = pack_bf16(h0, h1);
        *(uint32_t*)(g_ah + ob1 + col) = pack_bf16(h2, h3);
        *(uint32_t*)(g_al + ob0 + col) = pack_bf16(o0 - h0, o1 - h1);
        *(uint32_t*)(g_al + ob1 + col) = pack_bf16(o2 - h2, o3 - h3);
    }
}

// ---------------------------------------------------------------------------
extern "C" void kernel_launch(void* const* d_in, const int* in_sizes, int n_in,
                              void* d_out, int out_size)
{
    const float* x  = (const float*)d_in[0];
    const float* wq = (const float*)d_in[1];
    const float* bq = (const float*)d_in[2];
    const float* wk = (const float*)d_in[3];
    const float* bk = (const float*)d_in[4];
    const float* wv = (const float*)d_in[5];
    const float* bv = (const float*)d_in[6];
    const float* wo = (const float*)d_in[7];
    const float* bo = (const float*)d_in[8];
    float* out = (float*)d_out;

    static bool attr_set = false;
    if (!attr_set) {
        cudaFuncSetAttribute(gemm_mma_kernel,
                             cudaFuncAttributeMaxDynamicSharedMemorySize, GSM_TOTAL);
        cudaFuncSetAttribute(attn_mma_kernel,
                             cudaFuncAttributeMaxDynamicSharedMemorySize, ASM_TOTAL);
        attr_set = true;
    }

    prep_w_kernel<<<dim3(1024, 4), 256>>>(wq, wk, wv, wo);
    split_x_kernel<<<8192, 256>>>(x);

    // Fused Q/K/V projections: blockIdx.z selects weight + destination
    gemm_mma_kernel<<<dim3(4, 128, 3), 256, GSM_TOTAL>>>(bq, bk, bv, nullptr, 0);

    transpose_v_kernel<<<dim3(16, NBATCH), 256>>>();              // Vt hi/lo

    attn_mma_kernel<<<dim3(8, NBATCH), 256, ASM_TOTAL>>>();       // O -> g_ah/g_al

    // Output projection (wsel=3, fp32 out)
    gemm_mma_kernel<<<dim3(4, 128, 1), 256, GSM_TOTAL>>>(bo, nullptr, nullptr, out, -1);
}